// round 3
// baseline (speedup 1.0000x reference)
#include <cuda_runtime.h>
#include <cuda_bf16.h>
#include <math.h>
#include <stdint.h>

// ---------------- problem constants ----------------
#define BB     64
#define HH     56
#define WW     56
#define CC     192
#define NHEADS 6
#define HD     32
#define WSZ    7
#define TOK    49
#define NWIN_I 64
#define SHIFT  3
#define NTOK   (BB*HH*WW)   // 200704
#define NWIN   (BB*NWIN_I)  // 4096
#define HIDDEN 768

// ---------------- scratch (device globals; no allocs allowed) ----------------
__device__ __nv_bfloat16 g_xw  [(size_t)NTOK*CC];
__device__ __nv_bfloat16 g_qkv [(size_t)NTOK*3*CC];
__device__ __nv_bfloat16 g_att [(size_t)NTOK*CC];
__device__ __nv_bfloat16 g_proj[(size_t)NTOK*CC];
__device__ float         g_x1  [(size_t)NTOK*CC];
__device__ __nv_bfloat16 g_ln2 [(size_t)NTOK*CC];
__device__ __nv_bfloat16 g_hid [(size_t)NTOK*HIDDEN];
__device__ __nv_bfloat16 g_wqkv [3*CC*CC];
__device__ __nv_bfloat16 g_wproj[CC*CC];
__device__ __nv_bfloat16 g_wfc1 [HIDDEN*CC];
__device__ __nv_bfloat16 g_wfc2 [CC*HIDDEN];

// ---------------- helpers ----------------
__device__ __forceinline__ uint32_t smem_u32(const void* p) {
    uint32_t a;
    asm("{ .reg .u64 t; cvta.to.shared.u64 t, %1; cvt.u32.u64 %0, t; }" : "=r"(a) : "l"(p));
    return a;
}
__device__ __forceinline__ float warp_sum(float v) {
    #pragma unroll
    for (int o = 16; o > 0; o >>= 1) v += __shfl_xor_sync(0xffffffffu, v, o);
    return v;
}
__device__ __forceinline__ float warp_max(float v) {
    #pragma unroll
    for (int o = 16; o > 0; o >>= 1) v = fmaxf(v, __shfl_xor_sync(0xffffffffu, v, o));
    return v;
}
__device__ __forceinline__ float gelu_exact(float x) {
    return 0.5f * x * (1.0f + erff(x * 0.70710678118654752f));
}
__device__ __forceinline__ void ldsm_x4(uint32_t* r, uint32_t addr) {
    asm volatile("ldmatrix.sync.aligned.m8n8.x4.shared.b16 {%0,%1,%2,%3}, [%4];"
                 : "=r"(r[0]), "=r"(r[1]), "=r"(r[2]), "=r"(r[3]) : "r"(addr));
}
__device__ __forceinline__ void mma16816(float* d, const uint32_t* a, uint32_t b0, uint32_t b1) {
    asm volatile(
        "mma.sync.aligned.m16n8k16.row.col.f32.bf16.bf16.f32 "
        "{%0,%1,%2,%3}, {%4,%5,%6,%7}, {%8,%9}, {%0,%1,%2,%3};"
        : "+f"(d[0]), "+f"(d[1]), "+f"(d[2]), "+f"(d[3])
        : "r"(a[0]), "r"(a[1]), "r"(a[2]), "r"(a[3]), "r"(b0), "r"(b1));
}

// ---------------- weight f32 -> bf16 ----------------
__global__ void k_f2b(const float* __restrict__ src, __nv_bfloat16* __restrict__ dst, int n) {
    int i = blockIdx.x * 256 + threadIdx.x;
    if (i < n) dst[i] = __float2bfloat16(src[i]);
}

// ---------------- LN1 + roll(-3,-3) + window partition -> bf16 ----------------
__global__ void k_ln1_shift_part(const float* __restrict__ x,
                                 const float* __restrict__ g,
                                 const float* __restrict__ b) {
    int w = blockIdx.x, c = threadIdx.x;
    int n = w / TOK, t = w % TOK;
    int img = n / NWIN_I, win = n % NWIN_I;
    int hs = (win / 8) * WSZ + t / WSZ;
    int ws = (win % 8) * WSZ + t % WSZ;
    int hsrc = (hs + SHIFT) % HH;
    int wsrc = (ws + SHIFT) % WW;
    float val = x[((size_t)img * (HH*WW) + hsrc * WW + wsrc) * CC + c];

    float s  = warp_sum(val);
    float s2 = warp_sum(val * val);
    __shared__ float sh1[6], sh2[6];
    int lane = c & 31, warp = c >> 5;
    if (lane == 0) { sh1[warp] = s; sh2[warp] = s2; }
    __syncthreads();
    float ts = 0.f, ts2 = 0.f;
    #pragma unroll
    for (int i = 0; i < 6; i++) { ts += sh1[i]; ts2 += sh2[i]; }
    float mean = ts * (1.0f / CC);
    float var  = ts2 * (1.0f / CC) - mean * mean;
    float inv  = rsqrtf(var + 1e-5f);
    g_xw[(size_t)w * CC + c] = __float2bfloat16((val - mean) * inv * g[c] + b[c]);
}

// ---------------- window reverse + roll(+3,+3) + residual + LN2 (fused) ----------------
__global__ void k_resid_ln2(const float* __restrict__ x,
                            const float* __restrict__ g,
                            const float* __restrict__ b) {
    int tok = blockIdx.x, c = threadIdx.x;
    int img = tok / (HH*WW);
    int hw  = tok % (HH*WW);
    int hh = hw / WW, ww = hw % WW;
    int hs = (hh + HH - SHIFT) % HH;
    int ws = (ww + WW - SHIFT) % WW;
    int win = (hs / WSZ) * 8 + (ws / WSZ);
    int t   = (hs % WSZ) * WSZ + (ws % WSZ);
    size_t widx = ((size_t)(img * NWIN_I + win) * TOK + t) * CC + c;
    float val = x[(size_t)tok * CC + c] + __bfloat162float(g_proj[widx]);
    g_x1[(size_t)tok * CC + c] = val;

    float s  = warp_sum(val);
    float s2 = warp_sum(val * val);
    __shared__ float sh1[6], sh2[6];
    int lane = c & 31, warp = c >> 5;
    if (lane == 0) { sh1[warp] = s; sh2[warp] = s2; }
    __syncthreads();
    float ts = 0.f, ts2 = 0.f;
    #pragma unroll
    for (int i = 0; i < 6; i++) { ts += sh1[i]; ts2 += sh2[i]; }
    float mean = ts * (1.0f / CC);
    float var  = ts2 * (1.0f / CC) - mean * mean;
    float inv  = rsqrtf(var + 1e-5f);
    g_ln2[(size_t)tok * CC + c] = __float2bfloat16((val - mean) * inv * g[c] + b[c]);
}

// ---------------- HMMA GEMM: C[M,N] = A[M,K] @ W[N,K]^T + bias ----------------
// BM=128, BN=64, BK=32. 256 threads = 8 warps, warp grid 4(M) x 2(N), warp tile 32x32.
// epi: 0 = bf16 out, 1 = bf16 + gelu, 2 = f32 + residual
#define ASTR 40   // padded row stride in bf16 elems (80 bytes)
#define BSTR 40

__global__ void __launch_bounds__(256) k_gemm_mma(
        const __nv_bfloat16* __restrict__ A, const __nv_bfloat16* __restrict__ W,
        const float* __restrict__ bias, const float* __restrict__ res,
        void* __restrict__ outp, int M, int N, int K, int epi) {
    __shared__ __nv_bfloat16 sA[128 * ASTR];
    __shared__ __nv_bfloat16 sB[64 * BSTR];

    int tid = threadIdx.x, lane = tid & 31, wid = tid >> 5;
    int warp_m = wid & 3, warp_n = wid >> 2;
    int gm0 = blockIdx.y * 128;
    int gn0 = blockIdx.x * 64;

    float acc[2][4][4];
    #pragma unroll
    for (int mi = 0; mi < 2; mi++)
        #pragma unroll
        for (int ni = 0; ni < 4; ni++)
            #pragma unroll
            for (int q = 0; q < 4; q++) acc[mi][ni][q] = 0.f;

    uint32_t sAu = smem_u32(sA), sBu = smem_u32(sB);
    uint32_t aAddr = sAu + ((warp_m * 32 + (lane & 15)) * ASTR + (lane >> 4) * 8) * 2;
    uint32_t bAddr = sBu + ((warp_n * 32 + (lane & 15)) * BSTR + (lane >> 4) * 8) * 2;

    // global load indices (A: 512 uint4, B: 256 uint4)
    int lrA = tid >> 2, lcA = (tid & 3) * 8;

    for (int k0 = 0; k0 < K; k0 += 32) {
        __syncthreads();
        #pragma unroll
        for (int j = 0; j < 2; j++) {
            int r = lrA + j * 64;
            uint4 v = *reinterpret_cast<const uint4*>(A + (size_t)(gm0 + r) * K + k0 + lcA);
            *reinterpret_cast<uint4*>(sA + r * ASTR + lcA) = v;
        }
        {
            uint4 v = *reinterpret_cast<const uint4*>(W + (size_t)(gn0 + lrA) * K + k0 + lcA);
            *reinterpret_cast<uint4*>(sB + lrA * BSTR + lcA) = v;
        }
        __syncthreads();

        #pragma unroll
        for (int ks = 0; ks < 2; ks++) {
            uint32_t a[2][4], b[2][4];
            #pragma unroll
            for (int mi = 0; mi < 2; mi++)
                ldsm_x4(a[mi], aAddr + (mi * 16 * ASTR + ks * 16) * 2);
            #pragma unroll
            for (int nj = 0; nj < 2; nj++)
                ldsm_x4(b[nj], bAddr + (nj * 16 * BSTR + ks * 16) * 2);
            #pragma unroll
            for (int mi = 0; mi < 2; mi++)
                #pragma unroll
                for (int ni = 0; ni < 4; ni++)
                    mma16816(acc[mi][ni], a[mi], b[ni >> 1][ni & 1], b[ni >> 1][2 + (ni & 1)]);
        }
    }

    // epilogue
    int row_base = gm0 + warp_m * 32 + (lane >> 2);
    int col_base = gn0 + warp_n * 32 + (lane & 3) * 2;

    #pragma unroll
    for (int mi = 0; mi < 2; mi++) {
        #pragma unroll
        for (int ni = 0; ni < 4; ni++) {
            int col = col_base + ni * 8;
            float bc0 = bias[col], bc1 = bias[col + 1];
            #pragma unroll
            for (int h = 0; h < 2; h++) {          // h=0: row, h=1: row+8
                int r = row_base + mi * 16 + h * 8;
                float v0 = acc[mi][ni][h * 2 + 0] + bc0;
                float v1 = acc[mi][ni][h * 2 + 1] + bc1;
                if (epi == 1) { v0 = gelu_exact(v0); v1 = gelu_exact(v1); }
                if (epi == 2) {
                    float* out = (float*)outp;
                    const float2 rv = *reinterpret_cast<const float2*>(res + (size_t)r * N + col);
                    float2 o; o.x = v0 + rv.x; o.y = v1 + rv.y;
                    *reinterpret_cast<float2*>(out + (size_t)r * N + col) = o;
                } else {
                    __nv_bfloat16* out = (__nv_bfloat16*)outp;
                    __nv_bfloat162 p = __floats2bfloat162_rn(v0, v1);
                    *reinterpret_cast<uint32_t*>(out + (size_t)r * N + col) =
                        *reinterpret_cast<uint32_t*>(&p);
                }
            }
        }
    }
}

// ---------------- windowed attention (bf16 IO, fp32 math) ----------------
__global__ void k_attn(const float* __restrict__ rpb,
                       const int*   __restrict__ relidx,
                       const float* __restrict__ amask) {
    int blk = blockIdx.x;
    int n = blk / NHEADS, h = blk % NHEADS;
    int win = n % NWIN_I;

    __shared__ float sq[TOK][HD], sk[TOK][HD], sv[TOK][HD];
    __shared__ float sp[4][TOK + 3];

    const __nv_bfloat16* base = g_qkv + (size_t)n * TOK * (3*CC);
    int tid = threadIdx.x;
    const float scale = 0.17677669529663687f;
    for (int i = tid; i < TOK * HD; i += 128) {
        int t = i / HD, d = i % HD;
        sq[t][d] = __bfloat162float(base[t*(3*CC) +        h*HD + d]) * scale;
        sk[t][d] = __bfloat162float(base[t*(3*CC) + CC   + h*HD + d]);
        sv[t][d] = __bfloat162float(base[t*(3*CC) + 2*CC + h*HD + d]);
    }
    __syncthreads();

    int warp = tid >> 5, lane = tid & 31;
    const float* mrow = amask + (size_t)win * TOK * TOK;

    for (int r = warp; r < TOK; r += 4) {
        float s0, s1 = -1e30f;
        {
            float a = 0.f;
            #pragma unroll
            for (int d = 0; d < HD; d++) a = fmaf(sq[r][d], sk[lane][d], a);
            s0 = a + rpb[relidx[r*TOK + lane] * NHEADS + h] + mrow[r*TOK + lane];
        }
        int t2 = lane + 32;
        if (t2 < TOK) {
            float a = 0.f;
            #pragma unroll
            for (int d = 0; d < HD; d++) a = fmaf(sq[r][d], sk[t2][d], a);
            s1 = a + rpb[relidx[r*TOK + t2] * NHEADS + h] + mrow[r*TOK + t2];
        }
        float mx = warp_max(fmaxf(s0, s1));
        float p0 = __expf(s0 - mx);
        float p1 = (t2 < TOK) ? __expf(s1 - mx) : 0.f;
        float sum = warp_sum(p0 + p1);
        float inv = 1.0f / sum;
        sp[warp][lane] = p0 * inv;
        if (t2 < TOK) sp[warp][t2] = p1 * inv;
        __syncwarp();

        float o = 0.f;
        #pragma unroll
        for (int t = 0; t < TOK; t++) o = fmaf(sp[warp][t], sv[t][lane], o);
        g_att[((size_t)n * TOK + r) * CC + h*HD + lane] = __float2bfloat16(o);
        __syncwarp();
    }
}

// ---------------- launch ----------------
extern "C" void kernel_launch(void* const* d_in, const int* in_sizes, int n_in,
                              void* d_out, int out_size) {
    const float* x       = (const float*)d_in[0];
    const float* norm1_g = (const float*)d_in[1];
    const float* norm1_b = (const float*)d_in[2];
    const float* qkv_w   = (const float*)d_in[3];
    const float* qkv_b   = (const float*)d_in[4];
    const float* rpb     = (const float*)d_in[5];
    const float* proj_w  = (const float*)d_in[6];
    const float* proj_b  = (const float*)d_in[7];
    const float* norm2_g = (const float*)d_in[8];
    const float* norm2_b = (const float*)d_in[9];
    const float* fc1_w   = (const float*)d_in[10];
    const float* fc1_b   = (const float*)d_in[11];
    const float* fc2_w   = (const float*)d_in[12];
    const float* fc2_b   = (const float*)d_in[13];
    const int*   relidx;
    const float* amask;
    if (in_sizes[14] == TOK * TOK) {
        relidx = (const int*)d_in[14];  amask = (const float*)d_in[15];
    } else {
        relidx = (const int*)d_in[15];  amask = (const float*)d_in[14];
    }
    float* out = (float*)d_out;

    __nv_bfloat16 *p_xw, *p_qkv, *p_att, *p_proj, *p_ln2, *p_hid;
    __nv_bfloat16 *p_wqkv, *p_wproj, *p_wfc1, *p_wfc2;
    float *p_x1;
    cudaGetSymbolAddress((void**)&p_xw,    g_xw);
    cudaGetSymbolAddress((void**)&p_qkv,   g_qkv);
    cudaGetSymbolAddress((void**)&p_att,   g_att);
    cudaGetSymbolAddress((void**)&p_proj,  g_proj);
    cudaGetSymbolAddress((void**)&p_x1,    g_x1);
    cudaGetSymbolAddress((void**)&p_ln2,   g_ln2);
    cudaGetSymbolAddress((void**)&p_hid,   g_hid);
    cudaGetSymbolAddress((void**)&p_wqkv,  g_wqkv);
    cudaGetSymbolAddress((void**)&p_wproj, g_wproj);
    cudaGetSymbolAddress((void**)&p_wfc1,  g_wfc1);
    cudaGetSymbolAddress((void**)&p_wfc2,  g_wfc2);

    // weights -> bf16
    k_f2b<<<(3*CC*CC + 255)/256, 256>>>(qkv_w,  p_wqkv,  3*CC*CC);
    k_f2b<<<(CC*CC + 255)/256, 256>>>(proj_w, p_wproj, CC*CC);
    k_f2b<<<(HIDDEN*CC + 255)/256, 256>>>(fc1_w, p_wfc1, HIDDEN*CC);
    k_f2b<<<(CC*HIDDEN + 255)/256, 256>>>(fc2_w, p_wfc2, CC*HIDDEN);

    // 1) LN1 + shift + window partition
    k_ln1_shift_part<<<NTOK, CC>>>(x, norm1_g, norm1_b);

    // 2) qkv: (NTOK,192) @ (576,192)^T -> bf16
    {
        dim3 grid((3*CC)/64, NTOK/128);
        k_gemm_mma<<<grid, 256>>>(p_xw, p_wqkv, qkv_b, nullptr, p_qkv, NTOK, 3*CC, CC, 0);
    }

    // 3) windowed attention
    k_attn<<<NWIN * NHEADS, 128>>>(rpb, relidx, amask);

    // 4) proj
    {
        dim3 grid(CC/64, NTOK/128);
        k_gemm_mma<<<grid, 256>>>(p_att, p_wproj, proj_b, nullptr, p_proj, NTOK, CC, CC, 0);
    }

    // 5) window reverse + roll + residual + LN2 (fused)
    k_resid_ln2<<<NTOK, CC>>>(x, norm2_g, norm2_b);

    // 6) fc1 + GELU
    {
        dim3 grid(HIDDEN/64, NTOK/128);
        k_gemm_mma<<<grid, 256>>>(p_ln2, p_wfc1, fc1_b, nullptr, p_hid, NTOK, HIDDEN, CC, 1);
    }

    // 7) fc2 + residual -> out (f32)
    {
        dim3 grid(CC/64, NTOK/128);
        k_gemm_mma<<<grid, 256>>>(p_hid, p_wfc2, fc2_b, p_x1, out, NTOK, CC, HIDDEN, 2);
    }
}

// round 4
// speedup vs baseline: 3.8634x; 3.8634x over previous
#include <cuda_runtime.h>
#include <cuda_bf16.h>
#include <math.h>
#include <stdint.h>

// ---------------- problem constants ----------------
#define BB     64
#define HH     56
#define WW     56
#define CC     192
#define NHEADS 6
#define HD     32
#define WSZ    7
#define TOK    49
#define NWIN_I 64
#define SHIFT  3
#define NTOK   (BB*HH*WW)   // 200704
#define NWIN   (BB*NWIN_I)  // 4096
#define HIDDEN 768

// ---------------- scratch (device globals; no allocs allowed) ----------------
__device__ __nv_bfloat16 g_xw  [(size_t)NTOK*CC];
__device__ __nv_bfloat16 g_qkv [(size_t)NTOK*3*CC];
__device__ __nv_bfloat16 g_att [(size_t)NTOK*CC];
__device__ __nv_bfloat16 g_proj[(size_t)NTOK*CC];
__device__ float         g_x1  [(size_t)NTOK*CC];
__device__ __nv_bfloat16 g_ln2 [(size_t)NTOK*CC];
__device__ __nv_bfloat16 g_hid [(size_t)NTOK*HIDDEN];
__device__ __nv_bfloat16 g_wqkv [3*CC*CC];
__device__ __nv_bfloat16 g_wproj[CC*CC];
__device__ __nv_bfloat16 g_wfc1 [HIDDEN*CC];
__device__ __nv_bfloat16 g_wfc2 [CC*HIDDEN];
__device__ float         g_bm  [NWIN_I*NHEADS*TOK*TOK];   // bias+mask table (3.7MB)

// ---------------- helpers ----------------
__device__ __forceinline__ uint32_t smem_u32(const void* p) {
    uint32_t a;
    asm("{ .reg .u64 t; cvta.to.shared.u64 t, %1; cvt.u32.u64 %0, t; }" : "=r"(a) : "l"(p));
    return a;
}
__device__ __forceinline__ float warp_sum(float v) {
    #pragma unroll
    for (int o = 16; o > 0; o >>= 1) v += __shfl_xor_sync(0xffffffffu, v, o);
    return v;
}
__device__ __forceinline__ float warp_max(float v) {
    #pragma unroll
    for (int o = 16; o > 0; o >>= 1) v = fmaxf(v, __shfl_xor_sync(0xffffffffu, v, o));
    return v;
}
__device__ __forceinline__ float gelu_exact(float x) {
    return 0.5f * x * (1.0f + erff(x * 0.70710678118654752f));
}
__device__ __forceinline__ void ldsm_x4(uint32_t* r, uint32_t addr) {
    asm volatile("ldmatrix.sync.aligned.m8n8.x4.shared.b16 {%0,%1,%2,%3}, [%4];"
                 : "=r"(r[0]), "=r"(r[1]), "=r"(r[2]), "=r"(r[3]) : "r"(addr));
}
__device__ __forceinline__ void mma16816(float* d, const uint32_t* a, uint32_t b0, uint32_t b1) {
    asm volatile(
        "mma.sync.aligned.m16n8k16.row.col.f32.bf16.bf16.f32 "
        "{%0,%1,%2,%3}, {%4,%5,%6,%7}, {%8,%9}, {%0,%1,%2,%3};"
        : "+f"(d[0]), "+f"(d[1]), "+f"(d[2]), "+f"(d[3])
        : "r"(a[0]), "r"(a[1]), "r"(a[2]), "r"(a[3]), "r"(b0), "r"(b1));
}
__device__ __forceinline__ void cpasync16(uint32_t smem, const void* gptr) {
    asm volatile("cp.async.cg.shared.global [%0], [%1], 16;" :: "r"(smem), "l"(gptr));
}
__device__ __forceinline__ void cpasync_commit() {
    asm volatile("cp.async.commit_group;" ::: "memory");
}
template<int N> __device__ __forceinline__ void cpasync_wait() {
    asm volatile("cp.async.wait_group %0;" :: "n"(N) : "memory");
}

// ---------------- weight f32 -> bf16 ----------------
__global__ void k_f2b(const float* __restrict__ src, __nv_bfloat16* __restrict__ dst, int n) {
    int i = blockIdx.x * 256 + threadIdx.x;
    if (i < n) dst[i] = __float2bfloat16(src[i]);
}

// ---------------- precompute bias+mask table ----------------
__global__ void k_bias(const float* __restrict__ rpb, const int* __restrict__ relidx,
                       const float* __restrict__ amask) {
    int wh = blockIdx.x;            // 0..383
    int win = wh / NHEADS, h = wh % NHEADS;
    for (int i = threadIdx.x; i < TOK*TOK; i += 256)
        g_bm[(size_t)wh * (TOK*TOK) + i] = rpb[relidx[i] * NHEADS + h] + amask[win * (TOK*TOK) + i];
}

// ---------------- LN1 + roll(-3,-3) + window partition -> bf16 (8 tokens/block) ----------------
__global__ void __launch_bounds__(CC) k_ln1_shift_part(const float* __restrict__ x,
                                 const float* __restrict__ g,
                                 const float* __restrict__ b) {
    int c = threadIdx.x;
    float gc = g[c], bc = b[c];
    __shared__ float sh1[6], sh2[6];
    int lane = c & 31, warp = c >> 5;

    #pragma unroll 1
    for (int it = 0; it < 8; it++) {
        int w = blockIdx.x * 8 + it;
        int n = w / TOK, t = w % TOK;
        int img = n / NWIN_I, win = n % NWIN_I;
        int hs = (win / 8) * WSZ + t / WSZ;
        int ws = (win % 8) * WSZ + t % WSZ;
        int hsrc = (hs + SHIFT) % HH;
        int wsrc = (ws + SHIFT) % WW;
        float val = x[((size_t)img * (HH*WW) + hsrc * WW + wsrc) * CC + c];

        float s  = warp_sum(val);
        float s2 = warp_sum(val * val);
        if (lane == 0) { sh1[warp] = s; sh2[warp] = s2; }
        __syncthreads();
        float ts = 0.f, ts2 = 0.f;
        #pragma unroll
        for (int i = 0; i < 6; i++) { ts += sh1[i]; ts2 += sh2[i]; }
        float mean = ts * (1.0f / CC);
        float var  = ts2 * (1.0f / CC) - mean * mean;
        float inv  = rsqrtf(var + 1e-5f);
        g_xw[(size_t)w * CC + c] = __float2bfloat16((val - mean) * inv * gc + bc);
        __syncthreads();
    }
}

// ---------------- window reverse + roll(+3,+3) + residual + LN2 (8 tokens/block) ----------------
__global__ void __launch_bounds__(CC) k_resid_ln2(const float* __restrict__ x,
                            const float* __restrict__ g,
                            const float* __restrict__ b) {
    int c = threadIdx.x;
    float gc = g[c], bc = b[c];
    __shared__ float sh1[6], sh2[6];
    int lane = c & 31, warp = c >> 5;

    #pragma unroll 1
    for (int it = 0; it < 8; it++) {
        int tok = blockIdx.x * 8 + it;
        int img = tok / (HH*WW);
        int hw  = tok % (HH*WW);
        int hh = hw / WW, ww = hw % WW;
        int hs = (hh + HH - SHIFT) % HH;
        int ws = (ww + WW - SHIFT) % WW;
        int win = (hs / WSZ) * 8 + (ws / WSZ);
        int t   = (hs % WSZ) * WSZ + (ws % WSZ);
        size_t widx = ((size_t)(img * NWIN_I + win) * TOK + t) * CC + c;
        float val = x[(size_t)tok * CC + c] + __bfloat162float(g_proj[widx]);
        g_x1[(size_t)tok * CC + c] = val;

        float s  = warp_sum(val);
        float s2 = warp_sum(val * val);
        if (lane == 0) { sh1[warp] = s; sh2[warp] = s2; }
        __syncthreads();
        float ts = 0.f, ts2 = 0.f;
        #pragma unroll
        for (int i = 0; i < 6; i++) { ts += sh1[i]; ts2 += sh2[i]; }
        float mean = ts * (1.0f / CC);
        float var  = ts2 * (1.0f / CC) - mean * mean;
        float inv  = rsqrtf(var + 1e-5f);
        g_ln2[(size_t)tok * CC + c] = __float2bfloat16((val - mean) * inv * gc + bc);
        __syncthreads();
    }
}

// ---------------- HMMA GEMM w/ cp.async double buffer ----------------
// C[M,N] = A[M,K] @ W[N,K]^T + bias. BM=128, BN=64, BK=32; 256 thr, warp grid 4x2.
// epi: 0 = bf16 out, 1 = bf16 + gelu, 2 = f32 + residual
#define ASTR 40
#define BSTR 40
#define A_ST (128*ASTR)   // elems per A stage
#define B_ST (64*BSTR)

__global__ void __launch_bounds__(256) k_gemm_mma(
        const __nv_bfloat16* __restrict__ A, const __nv_bfloat16* __restrict__ W,
        const float* __restrict__ bias, const float* __restrict__ res,
        void* __restrict__ outp, int M, int N, int K, int epi) {
    __shared__ __nv_bfloat16 sA[2*A_ST];
    __shared__ __nv_bfloat16 sB[2*B_ST];

    int tid = threadIdx.x, lane = tid & 31, wid = tid >> 5;
    int warp_m = wid & 3, warp_n = wid >> 2;
    int gm0 = blockIdx.y * 128;
    int gn0 = blockIdx.x * 64;

    float acc[2][4][4];
    #pragma unroll
    for (int mi = 0; mi < 2; mi++)
        #pragma unroll
        for (int ni = 0; ni < 4; ni++)
            #pragma unroll
            for (int q = 0; q < 4; q++) acc[mi][ni][q] = 0.f;

    uint32_t sAu = smem_u32(sA), sBu = smem_u32(sB);
    int lrA = tid >> 2, lcA = (tid & 3) * 8;

    const __nv_bfloat16* Ag = A + (size_t)gm0 * K + lrA * (size_t)K + lcA;
    const __nv_bfloat16* Wg = W + (size_t)gn0 * K + lrA * (size_t)K + lcA;
    uint32_t sa_w = sAu + (lrA * ASTR + lcA) * 2;
    uint32_t sb_w = sBu + (lrA * BSTR + lcA) * 2;

    int nk = K >> 5;
    // prologue: stage 0
    cpasync16(sa_w,              Ag);
    cpasync16(sa_w + 64*ASTR*2,  Ag + (size_t)64 * K);
    cpasync16(sb_w,              Wg);
    cpasync_commit();

    for (int ch = 0; ch < nk; ch++) {
        int st = ch & 1;
        if (ch + 1 < nk) {
            int st2 = st ^ 1;
            const __nv_bfloat16* Ag2 = Ag + (ch + 1) * 32;
            const __nv_bfloat16* Wg2 = Wg + (ch + 1) * 32;
            cpasync16(sa_w + st2 * A_ST * 2,             Ag2);
            cpasync16(sa_w + (st2 * A_ST + 64*ASTR) * 2, Ag2 + (size_t)64 * K);
            cpasync16(sb_w + st2 * B_ST * 2,             Wg2);
            cpasync_commit();
            cpasync_wait<1>();
        } else {
            cpasync_wait<0>();
        }
        __syncthreads();

        uint32_t aAddr = sAu + (st * A_ST + (warp_m * 32 + (lane & 15)) * ASTR + (lane >> 4) * 8) * 2;
        uint32_t bAddr = sBu + (st * B_ST + (warp_n * 32 + (lane & 15)) * BSTR + (lane >> 4) * 8) * 2;
        #pragma unroll
        for (int ks = 0; ks < 2; ks++) {
            uint32_t a[2][4], b[2][4];
            #pragma unroll
            for (int mi = 0; mi < 2; mi++)
                ldsm_x4(a[mi], aAddr + (mi * 16 * ASTR + ks * 16) * 2);
            #pragma unroll
            for (int nj = 0; nj < 2; nj++)
                ldsm_x4(b[nj], bAddr + (nj * 16 * BSTR + ks * 16) * 2);
            #pragma unroll
            for (int mi = 0; mi < 2; mi++)
                #pragma unroll
                for (int ni = 0; ni < 4; ni++)
                    mma16816(acc[mi][ni], a[mi], b[ni >> 1][ni & 1], b[ni >> 1][2 + (ni & 1)]);
        }
        __syncthreads();
    }

    // epilogue
    int row_base = gm0 + warp_m * 32 + (lane >> 2);
    int col_base = gn0 + warp_n * 32 + (lane & 3) * 2;

    #pragma unroll
    for (int mi = 0; mi < 2; mi++) {
        #pragma unroll
        for (int ni = 0; ni < 4; ni++) {
            int col = col_base + ni * 8;
            float bc0 = bias[col], bc1 = bias[col + 1];
            #pragma unroll
            for (int h = 0; h < 2; h++) {
                int r = row_base + mi * 16 + h * 8;
                float v0 = acc[mi][ni][h * 2 + 0] + bc0;
                float v1 = acc[mi][ni][h * 2 + 1] + bc1;
                if (epi == 1) { v0 = gelu_exact(v0); v1 = gelu_exact(v1); }
                if (epi == 2) {
                    float* out = (float*)outp;
                    const float2 rv = *reinterpret_cast<const float2*>(res + (size_t)r * N + col);
                    float2 o; o.x = v0 + rv.x; o.y = v1 + rv.y;
                    *reinterpret_cast<float2*>(out + (size_t)r * N + col) = o;
                } else {
                    __nv_bfloat16* out = (__nv_bfloat16*)outp;
                    __nv_bfloat162 p = __floats2bfloat162_rn(v0, v1);
                    *reinterpret_cast<uint32_t*>(out + (size_t)r * N + col) =
                        *reinterpret_cast<uint32_t*>(&p);
                }
            }
        }
    }
}

// ---------------- windowed attention (bias+mask table, linear loads) ----------------
__global__ void __launch_bounds__(128) k_attn() {
    int blk = blockIdx.x;
    int n = blk / NHEADS, h = blk % NHEADS;
    int win = n % NWIN_I;

    __shared__ float sq[TOK][HD], sk[TOK][HD], sv[TOK][HD];
    __shared__ float sp[4][TOK + 3];

    const __nv_bfloat16* base = g_qkv + (size_t)n * TOK * (3*CC) + h * HD;
    int tid = threadIdx.x;
    const float scale = 0.17677669529663687f;
    for (int i = tid; i < TOK * (HD/2); i += 128) {
        int t = i >> 4, d2 = (i & 15) * 2;
        const __nv_bfloat16* p = base + t * (3*CC) + d2;
        float2 q2 = __bfloat1622float2(*reinterpret_cast<const __nv_bfloat162*>(p));
        float2 k2 = __bfloat1622float2(*reinterpret_cast<const __nv_bfloat162*>(p + CC));
        float2 v2 = __bfloat1622float2(*reinterpret_cast<const __nv_bfloat162*>(p + 2*CC));
        sq[t][d2] = q2.x * scale; sq[t][d2+1] = q2.y * scale;
        sk[t][d2] = k2.x;         sk[t][d2+1] = k2.y;
        sv[t][d2] = v2.x;         sv[t][d2+1] = v2.y;
    }
    __syncthreads();

    int warp = tid >> 5, lane = tid & 31;
    const float* bmrow = g_bm + (size_t)(win * NHEADS + h) * (TOK*TOK);

    for (int r = warp; r < TOK; r += 4) {
        float s0, s1 = -1e30f;
        {
            float a = bmrow[r*TOK + lane];
            #pragma unroll
            for (int d = 0; d < HD; d++) a = fmaf(sq[r][d], sk[lane][d], a);
            s0 = a;
        }
        int t2 = lane + 32;
        if (t2 < TOK) {
            float a = bmrow[r*TOK + t2];
            #pragma unroll
            for (int d = 0; d < HD; d++) a = fmaf(sq[r][d], sk[t2][d], a);
            s1 = a;
        }
        float mx = warp_max(fmaxf(s0, s1));
        float p0 = __expf(s0 - mx);
        float p1 = (t2 < TOK) ? __expf(s1 - mx) : 0.f;
        float sum = warp_sum(p0 + p1);
        float inv = 1.0f / sum;
        sp[warp][lane] = p0 * inv;
        if (t2 < TOK) sp[warp][t2] = p1 * inv;
        __syncwarp();

        float o = 0.f;
        #pragma unroll
        for (int t = 0; t < TOK; t++) o = fmaf(sp[warp][t], sv[t][lane], o);
        g_att[((size_t)n * TOK + r) * CC + h*HD + lane] = __float2bfloat16(o);
        __syncwarp();
    }
}

// ---------------- launch ----------------
extern "C" void kernel_launch(void* const* d_in, const int* in_sizes, int n_in,
                              void* d_out, int out_size) {
    const float* x       = (const float*)d_in[0];
    const float* norm1_g = (const float*)d_in[1];
    const float* norm1_b = (const float*)d_in[2];
    const float* qkv_w   = (const float*)d_in[3];
    const float* qkv_b   = (const float*)d_in[4];
    const float* rpb     = (const float*)d_in[5];
    const float* proj_w  = (const float*)d_in[6];
    const float* proj_b  = (const float*)d_in[7];
    const float* norm2_g = (const float*)d_in[8];
    const float* norm2_b = (const float*)d_in[9];
    const float* fc1_w   = (const float*)d_in[10];
    const float* fc1_b   = (const float*)d_in[11];
    const float* fc2_w   = (const float*)d_in[12];
    const float* fc2_b   = (const float*)d_in[13];
    const int*   relidx;
    const float* amask;
    if (in_sizes[14] == TOK * TOK) {
        relidx = (const int*)d_in[14];  amask = (const float*)d_in[15];
    } else {
        relidx = (const int*)d_in[15];  amask = (const float*)d_in[14];
    }
    float* out = (float*)d_out;

    __nv_bfloat16 *p_xw, *p_qkv, *p_att, *p_proj, *p_ln2, *p_hid;
    __nv_bfloat16 *p_wqkv, *p_wproj, *p_wfc1, *p_wfc2;
    float *p_x1;
    cudaGetSymbolAddress((void**)&p_xw,    g_xw);
    cudaGetSymbolAddress((void**)&p_qkv,   g_qkv);
    cudaGetSymbolAddress((void**)&p_att,   g_att);
    cudaGetSymbolAddress((void**)&p_proj,  g_proj);
    cudaGetSymbolAddress((void**)&p_x1,    g_x1);
    cudaGetSymbolAddress((void**)&p_ln2,   g_ln2);
    cudaGetSymbolAddress((void**)&p_hid,   g_hid);
    cudaGetSymbolAddress((void**)&p_wqkv,  g_wqkv);
    cudaGetSymbolAddress((void**)&p_wproj, g_wproj);
    cudaGetSymbolAddress((void**)&p_wfc1,  g_wfc1);
    cudaGetSymbolAddress((void**)&p_wfc2,  g_wfc2);

    // weights -> bf16, bias+mask table
    k_f2b<<<(3*CC*CC + 255)/256, 256>>>(qkv_w,  p_wqkv,  3*CC*CC);
    k_f2b<<<(CC*CC + 255)/256, 256>>>(proj_w, p_wproj, CC*CC);
    k_f2b<<<(HIDDEN*CC + 255)/256, 256>>>(fc1_w, p_wfc1, HIDDEN*CC);
    k_f2b<<<(CC*HIDDEN + 255)/256, 256>>>(fc2_w, p_wfc2, CC*HIDDEN);
    k_bias<<<NWIN_I*NHEADS, 256>>>(rpb, relidx, amask);

    // 1) LN1 + shift + window partition
    k_ln1_shift_part<<<NTOK/8, CC>>>(x, norm1_g, norm1_b);

    // 2) qkv
    {
        dim3 grid((3*CC)/64, NTOK/128);
        k_gemm_mma<<<grid, 256>>>(p_xw, p_wqkv, qkv_b, nullptr, p_qkv, NTOK, 3*CC, CC, 0);
    }

    // 3) windowed attention
    k_attn<<<NWIN * NHEADS, 128>>>();

    // 4) proj
    {
        dim3 grid(CC/64, NTOK/128);
        k_gemm_mma<<<grid, 256>>>(p_att, p_wproj, proj_b, nullptr, p_proj, NTOK, CC, CC, 0);
    }

    // 5) window reverse + roll + residual + LN2 (fused)
    k_resid_ln2<<<NTOK/8, CC>>>(x, norm2_g, norm2_b);

    // 6) fc1 + GELU
    {
        dim3 grid(HIDDEN/64, NTOK/128);
        k_gemm_mma<<<grid, 256>>>(p_ln2, p_wfc1, fc1_b, nullptr, p_hid, NTOK, HIDDEN, CC, 1);
    }

    // 7) fc2 + residual -> out (f32)
    {
        dim3 grid(CC/64, NTOK/128);
        k_gemm_mma<<<grid, 256>>>(p_hid, p_wfc2, fc2_b, p_x1, out, NTOK, CC, HIDDEN, 2);
    }
}

// round 5
// speedup vs baseline: 3.8976x; 1.0089x over previous
#include <cuda_runtime.h>
#include <cuda_bf16.h>
#include <math.h>
#include <stdint.h>

// ---------------- problem constants ----------------
#define BB     64
#define HH     56
#define WW     56
#define CC     192
#define NHEADS 6
#define HD     32
#define WSZ    7
#define TOK    49
#define NWIN_I 64
#define SHIFT  3
#define NTOK   (BB*HH*WW)   // 200704
#define NWIN   (BB*NWIN_I)  // 4096
#define HIDDEN 768

// ---------------- scratch (device globals; no allocs allowed) ----------------
__device__ __nv_bfloat16 g_xw  [(size_t)NTOK*CC];
__device__ __nv_bfloat16 g_qkv [(size_t)NTOK*3*CC];
__device__ __nv_bfloat16 g_att [(size_t)NTOK*CC];
__device__ __nv_bfloat16 g_proj[(size_t)NTOK*CC];
__device__ float         g_x1  [(size_t)NTOK*CC];
__device__ __nv_bfloat16 g_ln2 [(size_t)NTOK*CC];
__device__ __nv_bfloat16 g_hid [(size_t)NTOK*HIDDEN];
__device__ __nv_bfloat16 g_wqkv [3*CC*CC];
__device__ __nv_bfloat16 g_wproj[CC*CC];
__device__ __nv_bfloat16 g_wfc1 [HIDDEN*CC];
__device__ __nv_bfloat16 g_wfc2 [CC*HIDDEN];
__device__ float         g_bm  [NWIN_I*NHEADS*TOK*TOK];   // bias+mask table (3.7MB)

// ---------------- helpers ----------------
__device__ __forceinline__ uint32_t smem_u32(const void* p) {
    uint32_t a;
    asm("{ .reg .u64 t; cvta.to.shared.u64 t, %1; cvt.u32.u64 %0, t; }" : "=r"(a) : "l"(p));
    return a;
}
__device__ __forceinline__ float warp_sum(float v) {
    #pragma unroll
    for (int o = 16; o > 0; o >>= 1) v += __shfl_xor_sync(0xffffffffu, v, o);
    return v;
}
__device__ __forceinline__ float warp_max(float v) {
    #pragma unroll
    for (int o = 16; o > 0; o >>= 1) v = fmaxf(v, __shfl_xor_sync(0xffffffffu, v, o));
    return v;
}
__device__ __forceinline__ float gelu_exact(float x) {
    return 0.5f * x * (1.0f + erff(x * 0.70710678118654752f));
}
__device__ __forceinline__ void ldsm_x4(uint32_t* r, uint32_t addr) {
    asm volatile("ldmatrix.sync.aligned.m8n8.x4.shared.b16 {%0,%1,%2,%3}, [%4];"
                 : "=r"(r[0]), "=r"(r[1]), "=r"(r[2]), "=r"(r[3]) : "r"(addr));
}
__device__ __forceinline__ void mma16816(float* d, const uint32_t* a, uint32_t b0, uint32_t b1) {
    asm volatile(
        "mma.sync.aligned.m16n8k16.row.col.f32.bf16.bf16.f32 "
        "{%0,%1,%2,%3}, {%4,%5,%6,%7}, {%8,%9}, {%0,%1,%2,%3};"
        : "+f"(d[0]), "+f"(d[1]), "+f"(d[2]), "+f"(d[3])
        : "r"(a[0]), "r"(a[1]), "r"(a[2]), "r"(a[3]), "r"(b0), "r"(b1));
}
__device__ __forceinline__ void cpasync16(uint32_t smem, const void* gptr) {
    asm volatile("cp.async.cg.shared.global [%0], [%1], 16;" :: "r"(smem), "l"(gptr));
}
__device__ __forceinline__ void cpasync_commit() {
    asm volatile("cp.async.commit_group;" ::: "memory");
}
template<int N> __device__ __forceinline__ void cpasync_wait() {
    asm volatile("cp.async.wait_group %0;" :: "n"(N) : "memory");
}

// ---------------- all weights f32 -> bf16 in one launch ----------------
#define NW_QKV (3*CC*CC)    // 110592
#define NW_PRJ (CC*CC)      // 36864
#define NW_FC1 (HIDDEN*CC)  // 147456
#define NW_FC2 (CC*HIDDEN)  // 147456
#define NW_ALL (NW_QKV+NW_PRJ+NW_FC1+NW_FC2)

__global__ void k_f2b_all(const float* __restrict__ qkv_w, const float* __restrict__ proj_w,
                          const float* __restrict__ fc1_w, const float* __restrict__ fc2_w) {
    int i = blockIdx.x * 256 + threadIdx.x;
    if (i < NW_QKV) { g_wqkv[i] = __float2bfloat16(qkv_w[i]); return; }
    i -= NW_QKV;
    if (i < NW_PRJ) { g_wproj[i] = __float2bfloat16(proj_w[i]); return; }
    i -= NW_PRJ;
    if (i < NW_FC1) { g_wfc1[i] = __float2bfloat16(fc1_w[i]); return; }
    i -= NW_FC1;
    if (i < NW_FC2) { g_wfc2[i] = __float2bfloat16(fc2_w[i]); }
}

// ---------------- precompute bias+mask table ----------------
__global__ void k_bias(const float* __restrict__ rpb, const int* __restrict__ relidx,
                       const float* __restrict__ amask) {
    int wh = blockIdx.x;            // 0..383
    int win = wh / NHEADS, h = wh % NHEADS;
    for (int i = threadIdx.x; i < TOK*TOK; i += 256)
        g_bm[(size_t)wh * (TOK*TOK) + i] = rpb[relidx[i] * NHEADS + h] + amask[win * (TOK*TOK) + i];
}

// ---------------- LN1 + roll(-3,-3) + window partition -> bf16 (8 tokens/block) ----------------
__global__ void __launch_bounds__(CC) k_ln1_shift_part(const float* __restrict__ x,
                                 const float* __restrict__ g,
                                 const float* __restrict__ b) {
    int c = threadIdx.x;
    float gc = g[c], bc = b[c];
    __shared__ float sh1[6], sh2[6];
    int lane = c & 31, warp = c >> 5;

    #pragma unroll 1
    for (int it = 0; it < 8; it++) {
        int w = blockIdx.x * 8 + it;
        int n = w / TOK, t = w % TOK;
        int img = n / NWIN_I, win = n % NWIN_I;
        int hs = (win / 8) * WSZ + t / WSZ;
        int ws = (win % 8) * WSZ + t % WSZ;
        int hsrc = (hs + SHIFT) % HH;
        int wsrc = (ws + SHIFT) % WW;
        float val = x[((size_t)img * (HH*WW) + hsrc * WW + wsrc) * CC + c];

        float s  = warp_sum(val);
        float s2 = warp_sum(val * val);
        if (lane == 0) { sh1[warp] = s; sh2[warp] = s2; }
        __syncthreads();
        float ts = 0.f, ts2 = 0.f;
        #pragma unroll
        for (int i = 0; i < 6; i++) { ts += sh1[i]; ts2 += sh2[i]; }
        float mean = ts * (1.0f / CC);
        float var  = ts2 * (1.0f / CC) - mean * mean;
        float inv  = rsqrtf(var + 1e-5f);
        g_xw[(size_t)w * CC + c] = __float2bfloat16((val - mean) * inv * gc + bc);
        __syncthreads();
    }
}

// ---------------- window reverse + roll(+3,+3) + residual + LN2 (8 tokens/block) ----------------
__global__ void __launch_bounds__(CC) k_resid_ln2(const float* __restrict__ x,
                            const float* __restrict__ g,
                            const float* __restrict__ b) {
    int c = threadIdx.x;
    float gc = g[c], bc = b[c];
    __shared__ float sh1[6], sh2[6];
    int lane = c & 31, warp = c >> 5;

    #pragma unroll 1
    for (int it = 0; it < 8; it++) {
        int tok = blockIdx.x * 8 + it;
        int img = tok / (HH*WW);
        int hw  = tok % (HH*WW);
        int hh = hw / WW, ww = hw % WW;
        int hs = (hh + HH - SHIFT) % HH;
        int ws = (ww + WW - SHIFT) % WW;
        int win = (hs / WSZ) * 8 + (ws / WSZ);
        int t   = (hs % WSZ) * WSZ + (ws % WSZ);
        size_t widx = ((size_t)(img * NWIN_I + win) * TOK + t) * CC + c;
        float val = x[(size_t)tok * CC + c] + __bfloat162float(g_proj[widx]);
        g_x1[(size_t)tok * CC + c] = val;

        float s  = warp_sum(val);
        float s2 = warp_sum(val * val);
        if (lane == 0) { sh1[warp] = s; sh2[warp] = s2; }
        __syncthreads();
        float ts = 0.f, ts2 = 0.f;
        #pragma unroll
        for (int i = 0; i < 6; i++) { ts += sh1[i]; ts2 += sh2[i]; }
        float mean = ts * (1.0f / CC);
        float var  = ts2 * (1.0f / CC) - mean * mean;
        float inv  = rsqrtf(var + 1e-5f);
        g_ln2[(size_t)tok * CC + c] = __float2bfloat16((val - mean) * inv * gc + bc);
        __syncthreads();
    }
}

// ---------------- HMMA GEMM, cp.async double buffer, ONE sync/iter ----------------
// C[M,N] = A[M,K] @ W[N,K]^T + bias. BM=128, BN=64, BK=32; 256 thr, warp grid 4x2.
// epi: 0 = bf16 out, 1 = bf16 + gelu, 2 = f32 + residual
#define ASTR 40
#define BSTR 40
#define A_ST (128*ASTR)
#define B_ST (64*BSTR)

__global__ void __launch_bounds__(256, 3) k_gemm_mma(
        const __nv_bfloat16* __restrict__ A, const __nv_bfloat16* __restrict__ W,
        const float* __restrict__ bias, const float* __restrict__ res,
        void* __restrict__ outp, int M, int N, int K, int epi) {
    __shared__ __nv_bfloat16 sA[2*A_ST];
    __shared__ __nv_bfloat16 sB[2*B_ST];

    int tid = threadIdx.x, lane = tid & 31, wid = tid >> 5;
    int warp_m = wid & 3, warp_n = wid >> 2;
    int gm0 = blockIdx.y * 128;
    int gn0 = blockIdx.x * 64;

    float acc[2][4][4];
    #pragma unroll
    for (int mi = 0; mi < 2; mi++)
        #pragma unroll
        for (int ni = 0; ni < 4; ni++)
            #pragma unroll
            for (int q = 0; q < 4; q++) acc[mi][ni][q] = 0.f;

    uint32_t sAu = smem_u32(sA), sBu = smem_u32(sB);
    int lrA = tid >> 2, lcA = (tid & 3) * 8;

    const __nv_bfloat16* Ag = A + (size_t)(gm0 + lrA) * K + lcA;
    const __nv_bfloat16* Wg = W + (size_t)(gn0 + lrA) * K + lcA;
    uint32_t sa_w = sAu + (lrA * ASTR + lcA) * 2;
    uint32_t sb_w = sBu + (lrA * BSTR + lcA) * 2;

    int nk = K >> 5;
    // prologue: stage 0
    cpasync16(sa_w,              Ag);
    cpasync16(sa_w + 64*ASTR*2,  Ag + (size_t)64 * K);
    cpasync16(sb_w,              Wg);
    cpasync_commit();

    for (int ch = 0; ch < nk; ch++) {
        int st = ch & 1;
        cpasync_wait<0>();          // stage st's data arrived
        __syncthreads();            // visible to all; all warps done with st^1 compute
        if (ch + 1 < nk) {
            int st2 = st ^ 1;
            const __nv_bfloat16* Ag2 = Ag + (ch + 1) * 32;
            const __nv_bfloat16* Wg2 = Wg + (ch + 1) * 32;
            cpasync16(sa_w + st2 * A_ST * 2,             Ag2);
            cpasync16(sa_w + (st2 * A_ST + 64*ASTR) * 2, Ag2 + (size_t)64 * K);
            cpasync16(sb_w + st2 * B_ST * 2,             Wg2);
            cpasync_commit();
        }

        uint32_t aAddr = sAu + (st * A_ST + (warp_m * 32 + (lane & 15)) * ASTR + (lane >> 4) * 8) * 2;
        uint32_t bAddr = sBu + (st * B_ST + (warp_n * 32 + (lane & 15)) * BSTR + (lane >> 4) * 8) * 2;
        #pragma unroll
        for (int ks = 0; ks < 2; ks++) {
            uint32_t a[2][4], b[2][4];
            #pragma unroll
            for (int mi = 0; mi < 2; mi++)
                ldsm_x4(a[mi], aAddr + (mi * 16 * ASTR + ks * 16) * 2);
            #pragma unroll
            for (int nj = 0; nj < 2; nj++)
                ldsm_x4(b[nj], bAddr + (nj * 16 * BSTR + ks * 16) * 2);
            #pragma unroll
            for (int mi = 0; mi < 2; mi++)
                #pragma unroll
                for (int ni = 0; ni < 4; ni++)
                    mma16816(acc[mi][ni], a[mi], b[ni >> 1][ni & 1], b[ni >> 1][2 + (ni & 1)]);
        }
    }

    // epilogue
    int row_base = gm0 + warp_m * 32 + (lane >> 2);
    int col_base = gn0 + warp_n * 32 + (lane & 3) * 2;

    #pragma unroll
    for (int mi = 0; mi < 2; mi++) {
        #pragma unroll
        for (int ni = 0; ni < 4; ni++) {
            int col = col_base + ni * 8;
            float bc0 = bias[col], bc1 = bias[col + 1];
            #pragma unroll
            for (int h = 0; h < 2; h++) {
                int r = row_base + mi * 16 + h * 8;
                float v0 = acc[mi][ni][h * 2 + 0] + bc0;
                float v1 = acc[mi][ni][h * 2 + 1] + bc1;
                if (epi == 1) { v0 = gelu_exact(v0); v1 = gelu_exact(v1); }
                if (epi == 2) {
                    float* out = (float*)outp;
                    const float2 rv = *reinterpret_cast<const float2*>(res + (size_t)r * N + col);
                    float2 o; o.x = v0 + rv.x; o.y = v1 + rv.y;
                    *reinterpret_cast<float2*>(out + (size_t)r * N + col) = o;
                } else {
                    __nv_bfloat16* out = (__nv_bfloat16*)outp;
                    __nv_bfloat162 p = __floats2bfloat162_rn(v0, v1);
                    *reinterpret_cast<uint32_t*>(out + (size_t)r * N + col) =
                        *reinterpret_cast<uint32_t*>(&p);
                }
            }
        }
    }
}

// ---------------- windowed attention (bias+mask table, linear loads) ----------------
__global__ void __launch_bounds__(128) k_attn() {
    int blk = blockIdx.x;
    int n = blk / NHEADS, h = blk % NHEADS;
    int win = n % NWIN_I;

    __shared__ float sq[TOK][HD], sk[TOK][HD], sv[TOK][HD];
    __shared__ float sp[4][TOK + 3];

    const __nv_bfloat16* base = g_qkv + (size_t)n * TOK * (3*CC) + h * HD;
    int tid = threadIdx.x;
    const float scale = 0.17677669529663687f;
    for (int i = tid; i < TOK * (HD/2); i += 128) {
        int t = i >> 4, d2 = (i & 15) * 2;
        const __nv_bfloat16* p = base + t * (3*CC) + d2;
        float2 q2 = __bfloat1622float2(*reinterpret_cast<const __nv_bfloat162*>(p));
        float2 k2 = __bfloat1622float2(*reinterpret_cast<const __nv_bfloat162*>(p + CC));
        float2 v2 = __bfloat1622float2(*reinterpret_cast<const __nv_bfloat162*>(p + 2*CC));
        sq[t][d2] = q2.x * scale; sq[t][d2+1] = q2.y * scale;
        sk[t][d2] = k2.x;         sk[t][d2+1] = k2.y;
        sv[t][d2] = v2.x;         sv[t][d2+1] = v2.y;
    }
    __syncthreads();

    int warp = tid >> 5, lane = tid & 31;
    const float* bmrow = g_bm + (size_t)(win * NHEADS + h) * (TOK*TOK);

    for (int r = warp; r < TOK; r += 4) {
        float s0, s1 = -1e30f;
        {
            float a = bmrow[r*TOK + lane];
            #pragma unroll
            for (int d = 0; d < HD; d++) a = fmaf(sq[r][d], sk[lane][d], a);
            s0 = a;
        }
        int t2 = lane + 32;
        if (t2 < TOK) {
            float a = bmrow[r*TOK + t2];
            #pragma unroll
            for (int d = 0; d < HD; d++) a = fmaf(sq[r][d], sk[t2][d], a);
            s1 = a;
        }
        float mx = warp_max(fmaxf(s0, s1));
        float p0 = __expf(s0 - mx);
        float p1 = (t2 < TOK) ? __expf(s1 - mx) : 0.f;
        float sum = warp_sum(p0 + p1);
        float inv = 1.0f / sum;
        sp[warp][lane] = p0 * inv;
        if (t2 < TOK) sp[warp][t2] = p1 * inv;
        __syncwarp();

        float o = 0.f;
        #pragma unroll
        for (int t = 0; t < TOK; t++) o = fmaf(sp[warp][t], sv[t][lane], o);
        g_att[((size_t)n * TOK + r) * CC + h*HD + lane] = __float2bfloat16(o);
        __syncwarp();
    }
}

// ---------------- launch ----------------
extern "C" void kernel_launch(void* const* d_in, const int* in_sizes, int n_in,
                              void* d_out, int out_size) {
    const float* x       = (const float*)d_in[0];
    const float* norm1_g = (const float*)d_in[1];
    const float* norm1_b = (const float*)d_in[2];
    const float* qkv_w   = (const float*)d_in[3];
    const float* qkv_b   = (const float*)d_in[4];
    const float* rpb     = (const float*)d_in[5];
    const float* proj_w  = (const float*)d_in[6];
    const float* proj_b  = (const float*)d_in[7];
    const float* norm2_g = (const float*)d_in[8];
    const float* norm2_b = (const float*)d_in[9];
    const float* fc1_w   = (const float*)d_in[10];
    const float* fc1_b   = (const float*)d_in[11];
    const float* fc2_w   = (const float*)d_in[12];
    const float* fc2_b   = (const float*)d_in[13];
    const int*   relidx;
    const float* amask;
    if (in_sizes[14] == TOK * TOK) {
        relidx = (const int*)d_in[14];  amask = (const float*)d_in[15];
    } else {
        relidx = (const int*)d_in[15];  amask = (const float*)d_in[14];
    }
    float* out = (float*)d_out;

    __nv_bfloat16 *p_xw, *p_qkv, *p_att, *p_proj, *p_ln2, *p_hid;
    __nv_bfloat16 *p_wqkv, *p_wproj, *p_wfc1, *p_wfc2;
    float *p_x1;
    cudaGetSymbolAddress((void**)&p_xw,    g_xw);
    cudaGetSymbolAddress((void**)&p_qkv,   g_qkv);
    cudaGetSymbolAddress((void**)&p_att,   g_att);
    cudaGetSymbolAddress((void**)&p_proj,  g_proj);
    cudaGetSymbolAddress((void**)&p_x1,    g_x1);
    cudaGetSymbolAddress((void**)&p_ln2,   g_ln2);
    cudaGetSymbolAddress((void**)&p_hid,   g_hid);
    cudaGetSymbolAddress((void**)&p_wqkv,  g_wqkv);
    cudaGetSymbolAddress((void**)&p_wproj, g_wproj);
    cudaGetSymbolAddress((void**)&p_wfc1,  g_wfc1);
    cudaGetSymbolAddress((void**)&p_wfc2,  g_wfc2);

    // (1) all weights -> bf16, (2) bias+mask table
    k_f2b_all<<<NW_ALL/256, 256>>>(qkv_w, proj_w, fc1_w, fc2_w);
    k_bias<<<NWIN_I*NHEADS, 256>>>(rpb, relidx, amask);

    // (3) LN1 + shift + window partition
    k_ln1_shift_part<<<NTOK/8, CC>>>(x, norm1_g, norm1_b);

    // (4) qkv
    {
        dim3 grid((3*CC)/64, NTOK/128);
        k_gemm_mma<<<grid, 256>>>(p_xw, p_wqkv, qkv_b, nullptr, p_qkv, NTOK, 3*CC, CC, 0);
    }

    // (5) windowed attention
    k_attn<<<NWIN * NHEADS, 128>>>();

    // (6) proj  <-- ncu -s 5 -c 1 captures this launch
    {
        dim3 grid(CC/64, NTOK/128);
        k_gemm_mma<<<grid, 256>>>(p_att, p_wproj, proj_b, nullptr, p_proj, NTOK, CC, CC, 0);
    }

    // (7) window reverse + roll + residual + LN2 (fused)
    k_resid_ln2<<<NTOK/8, CC>>>(x, norm2_g, norm2_b);

    // (8) fc1 + GELU
    {
        dim3 grid(HIDDEN/64, NTOK/128);
        k_gemm_mma<<<grid, 256>>>(p_ln2, p_wfc1, fc1_b, nullptr, p_hid, NTOK, HIDDEN, CC, 1);
    }

    // (9) fc2 + residual -> out (f32)
    {
        dim3 grid(CC/64, NTOK/128);
        k_gemm_mma<<<grid, 256>>>(p_hid, p_wfc2, fc2_b, p_x1, out, NTOK, CC, HIDDEN, 2);
    }
}

// round 6
// speedup vs baseline: 5.8755x; 1.5075x over previous
#include <cuda_runtime.h>
#include <cuda_bf16.h>
#include <math.h>
#include <stdint.h>

// ---------------- problem constants ----------------
#define BB     64
#define HH     56
#define WW     56
#define CC     192
#define NHEADS 6
#define HD     32
#define HDP    33          // padded stride (bank-conflict-free)
#define WSZ    7
#define TOK    49
#define NWIN_I 64
#define SHIFT  3
#define NTOK   (BB*HH*WW)   // 200704
#define NWIN   (BB*NWIN_I)  // 4096
#define HIDDEN 768

// ---------------- scratch (device globals; no allocs allowed) ----------------
__device__ __nv_bfloat16 g_xw  [(size_t)NTOK*CC];
__device__ __nv_bfloat16 g_qkv [(size_t)NTOK*3*CC];
__device__ __nv_bfloat16 g_att [(size_t)NTOK*CC];
__device__ __nv_bfloat16 g_proj[(size_t)NTOK*CC];
__device__ float         g_x1  [(size_t)NTOK*CC];
__device__ __nv_bfloat16 g_ln2 [(size_t)NTOK*CC];
__device__ __nv_bfloat16 g_hid [(size_t)NTOK*HIDDEN];
__device__ __nv_bfloat16 g_wqkv [3*CC*CC];
__device__ __nv_bfloat16 g_wproj[CC*CC];
__device__ __nv_bfloat16 g_wfc1 [HIDDEN*CC];
__device__ __nv_bfloat16 g_wfc2 [CC*HIDDEN];
__device__ float         g_bm  [NWIN_I*NHEADS*TOK*TOK];   // bias+mask table (3.7MB)

// ---------------- helpers ----------------
__device__ __forceinline__ uint32_t smem_u32(const void* p) {
    uint32_t a;
    asm("{ .reg .u64 t; cvta.to.shared.u64 t, %1; cvt.u32.u64 %0, t; }" : "=r"(a) : "l"(p));
    return a;
}
__device__ __forceinline__ float warp_sum(float v) {
    #pragma unroll
    for (int o = 16; o > 0; o >>= 1) v += __shfl_xor_sync(0xffffffffu, v, o);
    return v;
}
__device__ __forceinline__ float warp_max(float v) {
    #pragma unroll
    for (int o = 16; o > 0; o >>= 1) v = fmaxf(v, __shfl_xor_sync(0xffffffffu, v, o));
    return v;
}
__device__ __forceinline__ float gelu_exact(float x) {
    return 0.5f * x * (1.0f + erff(x * 0.70710678118654752f));
}
__device__ __forceinline__ void ldsm_x4(uint32_t* r, uint32_t addr) {
    asm volatile("ldmatrix.sync.aligned.m8n8.x4.shared.b16 {%0,%1,%2,%3}, [%4];"
                 : "=r"(r[0]), "=r"(r[1]), "=r"(r[2]), "=r"(r[3]) : "r"(addr));
}
__device__ __forceinline__ void mma16816(float* d, const uint32_t* a, uint32_t b0, uint32_t b1) {
    asm volatile(
        "mma.sync.aligned.m16n8k16.row.col.f32.bf16.bf16.f32 "
        "{%0,%1,%2,%3}, {%4,%5,%6,%7}, {%8,%9}, {%0,%1,%2,%3};"
        : "+f"(d[0]), "+f"(d[1]), "+f"(d[2]), "+f"(d[3])
        : "r"(a[0]), "r"(a[1]), "r"(a[2]), "r"(a[3]), "r"(b0), "r"(b1));
}
__device__ __forceinline__ void cpasync16(uint32_t smem, const void* gptr) {
    asm volatile("cp.async.cg.shared.global [%0], [%1], 16;" :: "r"(smem), "l"(gptr));
}
__device__ __forceinline__ void cpasync_commit() {
    asm volatile("cp.async.commit_group;" ::: "memory");
}
template<int N> __device__ __forceinline__ void cpasync_wait() {
    asm volatile("cp.async.wait_group %0;" :: "n"(N) : "memory");
}

// ---------------- all weights f32 -> bf16 in one launch ----------------
#define NW_QKV (3*CC*CC)
#define NW_PRJ (CC*CC)
#define NW_FC1 (HIDDEN*CC)
#define NW_FC2 (CC*HIDDEN)
#define NW_ALL (NW_QKV+NW_PRJ+NW_FC1+NW_FC2)

__global__ void k_f2b_all(const float* __restrict__ qkv_w, const float* __restrict__ proj_w,
                          const float* __restrict__ fc1_w, const float* __restrict__ fc2_w) {
    int i = blockIdx.x * 256 + threadIdx.x;
    if (i < NW_QKV) { g_wqkv[i] = __float2bfloat16(qkv_w[i]); return; }
    i -= NW_QKV;
    if (i < NW_PRJ) { g_wproj[i] = __float2bfloat16(proj_w[i]); return; }
    i -= NW_PRJ;
    if (i < NW_FC1) { g_wfc1[i] = __float2bfloat16(fc1_w[i]); return; }
    i -= NW_FC1;
    if (i < NW_FC2) { g_wfc2[i] = __float2bfloat16(fc2_w[i]); }
}

// ---------------- precompute bias+mask table ----------------
__global__ void k_bias(const float* __restrict__ rpb, const int* __restrict__ relidx,
                       const float* __restrict__ amask) {
    int wh = blockIdx.x;
    int win = wh / NHEADS, h = wh % NHEADS;
    for (int i = threadIdx.x; i < TOK*TOK; i += 256)
        g_bm[(size_t)wh * (TOK*TOK) + i] = rpb[relidx[i] * NHEADS + h] + amask[win * (TOK*TOK) + i];
}

// ---------------- LN1 + roll(-3,-3) + window partition -> bf16 (8 tokens/block) ----------------
__global__ void __launch_bounds__(CC) k_ln1_shift_part(const float* __restrict__ x,
                                 const float* __restrict__ g,
                                 const float* __restrict__ b) {
    int c = threadIdx.x;
    float gc = g[c], bc = b[c];
    __shared__ float sh1[6], sh2[6];
    int lane = c & 31, warp = c >> 5;

    #pragma unroll 1
    for (int it = 0; it < 8; it++) {
        int w = blockIdx.x * 8 + it;
        int n = w / TOK, t = w % TOK;
        int img = n / NWIN_I, win = n % NWIN_I;
        int hs = (win / 8) * WSZ + t / WSZ;
        int ws = (win % 8) * WSZ + t % WSZ;
        int hsrc = (hs + SHIFT) % HH;
        int wsrc = (ws + SHIFT) % WW;
        float val = x[((size_t)img * (HH*WW) + hsrc * WW + wsrc) * CC + c];

        float s  = warp_sum(val);
        float s2 = warp_sum(val * val);
        if (lane == 0) { sh1[warp] = s; sh2[warp] = s2; }
        __syncthreads();
        float ts = 0.f, ts2 = 0.f;
        #pragma unroll
        for (int i = 0; i < 6; i++) { ts += sh1[i]; ts2 += sh2[i]; }
        float mean = ts * (1.0f / CC);
        float var  = ts2 * (1.0f / CC) - mean * mean;
        float inv  = rsqrtf(var + 1e-5f);
        g_xw[(size_t)w * CC + c] = __float2bfloat16((val - mean) * inv * gc + bc);
        __syncthreads();
    }
}

// ---------------- window reverse + roll(+3,+3) + residual + LN2 (8 tokens/block) ----------------
__global__ void __launch_bounds__(CC) k_resid_ln2(const float* __restrict__ x,
                            const float* __restrict__ g,
                            const float* __restrict__ b) {
    int c = threadIdx.x;
    float gc = g[c], bc = b[c];
    __shared__ float sh1[6], sh2[6];
    int lane = c & 31, warp = c >> 5;

    #pragma unroll 1
    for (int it = 0; it < 8; it++) {
        int tok = blockIdx.x * 8 + it;
        int img = tok / (HH*WW);
        int hw  = tok % (HH*WW);
        int hh = hw / WW, ww = hw % WW;
        int hs = (hh + HH - SHIFT) % HH;
        int ws = (ww + WW - SHIFT) % WW;
        int win = (hs / WSZ) * 8 + (ws / WSZ);
        int t   = (hs % WSZ) * WSZ + (ws % WSZ);
        size_t widx = ((size_t)(img * NWIN_I + win) * TOK + t) * CC + c;
        float val = x[(size_t)tok * CC + c] + __bfloat162float(g_proj[widx]);
        g_x1[(size_t)tok * CC + c] = val;

        float s  = warp_sum(val);
        float s2 = warp_sum(val * val);
        if (lane == 0) { sh1[warp] = s; sh2[warp] = s2; }
        __syncthreads();
        float ts = 0.f, ts2 = 0.f;
        #pragma unroll
        for (int i = 0; i < 6; i++) { ts += sh1[i]; ts2 += sh2[i]; }
        float mean = ts * (1.0f / CC);
        float var  = ts2 * (1.0f / CC) - mean * mean;
        float inv  = rsqrtf(var + 1e-5f);
        g_ln2[(size_t)tok * CC + c] = __float2bfloat16((val - mean) * inv * gc + bc);
        __syncthreads();
    }
}

// ---------------- HMMA GEMM, cp.async double buffer, ONE sync/iter ----------------
#define ASTR 40
#define BSTR 40
#define A_ST (128*ASTR)
#define B_ST (64*BSTR)

__global__ void __launch_bounds__(256, 3) k_gemm_mma(
        const __nv_bfloat16* __restrict__ A, const __nv_bfloat16* __restrict__ W,
        const float* __restrict__ bias, const float* __restrict__ res,
        void* __restrict__ outp, int M, int N, int K, int epi) {
    __shared__ __nv_bfloat16 sA[2*A_ST];
    __shared__ __nv_bfloat16 sB[2*B_ST];

    int tid = threadIdx.x, lane = tid & 31, wid = tid >> 5;
    int warp_m = wid & 3, warp_n = wid >> 2;
    int gm0 = blockIdx.y * 128;
    int gn0 = blockIdx.x * 64;

    float acc[2][4][4];
    #pragma unroll
    for (int mi = 0; mi < 2; mi++)
        #pragma unroll
        for (int ni = 0; ni < 4; ni++)
            #pragma unroll
            for (int q = 0; q < 4; q++) acc[mi][ni][q] = 0.f;

    uint32_t sAu = smem_u32(sA), sBu = smem_u32(sB);
    int lrA = tid >> 2, lcA = (tid & 3) * 8;

    const __nv_bfloat16* Ag = A + (size_t)(gm0 + lrA) * K + lcA;
    const __nv_bfloat16* Wg = W + (size_t)(gn0 + lrA) * K + lcA;
    uint32_t sa_w = sAu + (lrA * ASTR + lcA) * 2;
    uint32_t sb_w = sBu + (lrA * BSTR + lcA) * 2;

    int nk = K >> 5;
    cpasync16(sa_w,              Ag);
    cpasync16(sa_w + 64*ASTR*2,  Ag + (size_t)64 * K);
    cpasync16(sb_w,              Wg);
    cpasync_commit();

    for (int ch = 0; ch < nk; ch++) {
        int st = ch & 1;
        cpasync_wait<0>();
        __syncthreads();
        if (ch + 1 < nk) {
            int st2 = st ^ 1;
            const __nv_bfloat16* Ag2 = Ag + (ch + 1) * 32;
            const __nv_bfloat16* Wg2 = Wg + (ch + 1) * 32;
            cpasync16(sa_w + st2 * A_ST * 2,             Ag2);
            cpasync16(sa_w + (st2 * A_ST + 64*ASTR) * 2, Ag2 + (size_t)64 * K);
            cpasync16(sb_w + st2 * B_ST * 2,             Wg2);
            cpasync_commit();
        }

        uint32_t aAddr = sAu + (st * A_ST + (warp_m * 32 + (lane & 15)) * ASTR + (lane >> 4) * 8) * 2;
        uint32_t bAddr = sBu + (st * B_ST + (warp_n * 32 + (lane & 15)) * BSTR + (lane >> 4) * 8) * 2;
        #pragma unroll
        for (int ks = 0; ks < 2; ks++) {
            uint32_t a[2][4], b[2][4];
            #pragma unroll
            for (int mi = 0; mi < 2; mi++)
                ldsm_x4(a[mi], aAddr + (mi * 16 * ASTR + ks * 16) * 2);
            #pragma unroll
            for (int nj = 0; nj < 2; nj++)
                ldsm_x4(b[nj], bAddr + (nj * 16 * BSTR + ks * 16) * 2);
            #pragma unroll
            for (int mi = 0; mi < 2; mi++)
                #pragma unroll
                for (int ni = 0; ni < 4; ni++)
                    mma16816(acc[mi][ni], a[mi], b[ni >> 1][ni & 1], b[ni >> 1][2 + (ni & 1)]);
        }
    }

    // epilogue
    int row_base = gm0 + warp_m * 32 + (lane >> 2);
    int col_base = gn0 + warp_n * 32 + (lane & 3) * 2;

    #pragma unroll
    for (int mi = 0; mi < 2; mi++) {
        #pragma unroll
        for (int ni = 0; ni < 4; ni++) {
            int col = col_base + ni * 8;
            float bc0 = bias[col], bc1 = bias[col + 1];
            #pragma unroll
            for (int h = 0; h < 2; h++) {
                int r = row_base + mi * 16 + h * 8;
                float v0 = acc[mi][ni][h * 2 + 0] + bc0;
                float v1 = acc[mi][ni][h * 2 + 1] + bc1;
                if (epi == 1) { v0 = gelu_exact(v0); v1 = gelu_exact(v1); }
                if (epi == 2) {
                    float* out = (float*)outp;
                    const float2 rv = *reinterpret_cast<const float2*>(res + (size_t)r * N + col);
                    float2 o; o.x = v0 + rv.x; o.y = v1 + rv.y;
                    *reinterpret_cast<float2*>(out + (size_t)r * N + col) = o;
                } else {
                    __nv_bfloat16* out = (__nv_bfloat16*)outp;
                    __nv_bfloat162 p = __floats2bfloat162_rn(v0, v1);
                    *reinterpret_cast<uint32_t*>(out + (size_t)r * N + col) =
                        *reinterpret_cast<uint32_t*>(&p);
                }
            }
        }
    }
}

// ---------------- windowed attention (padded smem: conflict-free) ----------------
__global__ void __launch_bounds__(128) k_attn() {
    int blk = blockIdx.x;
    int n = blk / NHEADS, h = blk % NHEADS;
    int win = n % NWIN_I;

    __shared__ float sq[TOK][HDP], sk[TOK][HDP], sv[TOK][HDP];
    __shared__ float sp[4][TOK + 3];

    const __nv_bfloat16* base = g_qkv + (size_t)n * TOK * (3*CC) + h * HD;
    int tid = threadIdx.x;
    const float scale = 0.17677669529663687f;
    for (int i = tid; i < TOK * (HD/2); i += 128) {
        int t = i >> 4, d2 = (i & 15) * 2;
        const __nv_bfloat16* p = base + t * (3*CC) + d2;
        float2 q2 = __bfloat1622float2(*reinterpret_cast<const __nv_bfloat162*>(p));
        float2 k2 = __bfloat1622float2(*reinterpret_cast<const __nv_bfloat162*>(p + CC));
        float2 v2 = __bfloat1622float2(*reinterpret_cast<const __nv_bfloat162*>(p + 2*CC));
        sq[t][d2] = q2.x * scale; sq[t][d2+1] = q2.y * scale;
        sk[t][d2] = k2.x;         sk[t][d2+1] = k2.y;
        sv[t][d2] = v2.x;         sv[t][d2+1] = v2.y;
    }
    __syncthreads();

    int warp = tid >> 5, lane = tid & 31;
    const float* bmrow = g_bm + (size_t)(win * NHEADS + h) * (TOK*TOK);

    for (int r = warp; r < TOK; r += 4) {
        float s0, s1 = -1e30f;
        {
            float a = bmrow[r*TOK + lane];
            #pragma unroll
            for (int d = 0; d < HD; d++) a = fmaf(sq[r][d], sk[lane][d], a);
            s0 = a;
        }
        int t2 = lane + 32;
        if (t2 < TOK) {
            float a = bmrow[r*TOK + t2];
            #pragma unroll
            for (int d = 0; d < HD; d++) a = fmaf(sq[r][d], sk[t2][d], a);
            s1 = a;
        }
        float mx = warp_max(fmaxf(s0, s1));
        float p0 = __expf(s0 - mx);
        float p1 = (t2 < TOK) ? __expf(s1 - mx) : 0.f;
        float sum = warp_sum(p0 + p1);
        float inv = 1.0f / sum;
        sp[warp][lane] = p0 * inv;
        if (t2 < TOK) sp[warp][t2] = p1 * inv;
        __syncwarp();

        float o = 0.f;
        #pragma unroll
        for (int t = 0; t < TOK; t++) o = fmaf(sp[warp][t], sv[t][lane], o);
        g_att[((size_t)n * TOK + r) * CC + h*HD + lane] = __float2bfloat16(o);
        __syncwarp();
    }
}

// ---------------- launch ----------------
extern "C" void kernel_launch(void* const* d_in, const int* in_sizes, int n_in,
                              void* d_out, int out_size) {
    const float* x       = (const float*)d_in[0];
    const float* norm1_g = (const float*)d_in[1];
    const float* norm1_b = (const float*)d_in[2];
    const float* qkv_w   = (const float*)d_in[3];
    const float* qkv_b   = (const float*)d_in[4];
    const float* rpb     = (const float*)d_in[5];
    const float* proj_w  = (const float*)d_in[6];
    const float* proj_b  = (const float*)d_in[7];
    const float* norm2_g = (const float*)d_in[8];
    const float* norm2_b = (const float*)d_in[9];
    const float* fc1_w   = (const float*)d_in[10];
    const float* fc1_b   = (const float*)d_in[11];
    const float* fc2_w   = (const float*)d_in[12];
    const float* fc2_b   = (const float*)d_in[13];
    const int*   relidx;
    const float* amask;
    if (in_sizes[14] == TOK * TOK) {
        relidx = (const int*)d_in[14];  amask = (const float*)d_in[15];
    } else {
        relidx = (const int*)d_in[15];  amask = (const float*)d_in[14];
    }
    float* out = (float*)d_out;

    __nv_bfloat16 *p_xw, *p_qkv, *p_att, *p_proj, *p_ln2, *p_hid;
    __nv_bfloat16 *p_wqkv, *p_wproj, *p_wfc1, *p_wfc2;
    float *p_x1;
    cudaGetSymbolAddress((void**)&p_xw,    g_xw);
    cudaGetSymbolAddress((void**)&p_qkv,   g_qkv);
    cudaGetSymbolAddress((void**)&p_att,   g_att);
    cudaGetSymbolAddress((void**)&p_proj,  g_proj);
    cudaGetSymbolAddress((void**)&p_x1,    g_x1);
    cudaGetSymbolAddress((void**)&p_ln2,   g_ln2);
    cudaGetSymbolAddress((void**)&p_hid,   g_hid);
    cudaGetSymbolAddress((void**)&p_wqkv,  g_wqkv);
    cudaGetSymbolAddress((void**)&p_wproj, g_wproj);
    cudaGetSymbolAddress((void**)&p_wfc1,  g_wfc1);
    cudaGetSymbolAddress((void**)&p_wfc2,  g_wfc2);

    k_f2b_all<<<NW_ALL/256, 256>>>(qkv_w, proj_w, fc1_w, fc2_w);
    k_bias<<<NWIN_I*NHEADS, 256>>>(rpb, relidx, amask);

    k_ln1_shift_part<<<NTOK/8, CC>>>(x, norm1_g, norm1_b);

    {
        dim3 grid((3*CC)/64, NTOK/128);
        k_gemm_mma<<<grid, 256>>>(p_xw, p_wqkv, qkv_b, nullptr, p_qkv, NTOK, 3*CC, CC, 0);
    }

    k_attn<<<NWIN * NHEADS, 128>>>();

    {
        dim3 grid(CC/64, NTOK/128);
        k_gemm_mma<<<grid, 256>>>(p_att, p_wproj, proj_b, nullptr, p_proj, NTOK, CC, CC, 0);
    }

    k_resid_ln2<<<NTOK/8, CC>>>(x, norm2_g, norm2_b);

    {
        dim3 grid(HIDDEN/64, NTOK/128);
        k_gemm_mma<<<grid, 256>>>(p_ln2, p_wfc1, fc1_b, nullptr, p_hid, NTOK, HIDDEN, CC, 1);
    }

    {
        dim3 grid(CC/64, NTOK/128);
        k_gemm_mma<<<grid, 256>>>(p_hid, p_wfc2, fc2_b, p_x1, out, NTOK, CC, HIDDEN, 2);
    }
}

// round 7
// speedup vs baseline: 8.5201x; 1.4501x over previous
#include <cuda_runtime.h>
#include <cuda_bf16.h>
#include <math.h>
#include <stdint.h>

// ---------------- problem constants ----------------
#define BB     64
#define HH     56
#define WW     56
#define CC     192
#define NHEADS 6
#define HD     32
#define WSZ    7
#define TOK    49
#define NWIN_I 64
#define SHIFT  3
#define NTOK   (BB*HH*WW)   // 200704
#define NWIN   (BB*NWIN_I)  // 4096
#define HIDDEN 768

// ---------------- scratch (device globals; no allocs allowed) ----------------
__device__ __nv_bfloat16 g_xw  [(size_t)NTOK*CC];
__device__ __nv_bfloat16 g_qkv [(size_t)NTOK*3*CC];
__device__ __nv_bfloat16 g_att [(size_t)NTOK*CC];
__device__ __nv_bfloat16 g_proj[(size_t)NTOK*CC];
__device__ float         g_x1  [(size_t)NTOK*CC];
__device__ __nv_bfloat16 g_ln2 [(size_t)NTOK*CC];
__device__ __nv_bfloat16 g_hid [(size_t)NTOK*HIDDEN];
__device__ __nv_bfloat16 g_wqkv [3*CC*CC];
__device__ __nv_bfloat16 g_wproj[CC*CC];
__device__ __nv_bfloat16 g_wfc1 [HIDDEN*CC];
__device__ __nv_bfloat16 g_wfc2 [CC*HIDDEN];
__device__ float         g_bm  [NWIN_I*NHEADS*TOK*TOK];   // bias+mask table (3.7MB)

// ---------------- helpers ----------------
__device__ __forceinline__ uint32_t smem_u32(const void* p) {
    uint32_t a;
    asm("{ .reg .u64 t; cvta.to.shared.u64 t, %1; cvt.u32.u64 %0, t; }" : "=r"(a) : "l"(p));
    return a;
}
__device__ __forceinline__ float warp_sum(float v) {
    #pragma unroll
    for (int o = 16; o > 0; o >>= 1) v += __shfl_xor_sync(0xffffffffu, v, o);
    return v;
}
__device__ __forceinline__ float warp_max(float v) {
    #pragma unroll
    for (int o = 16; o > 0; o >>= 1) v = fmaxf(v, __shfl_xor_sync(0xffffffffu, v, o));
    return v;
}
__device__ __forceinline__ float gelu_exact(float x) {
    return 0.5f * x * (1.0f + erff(x * 0.70710678118654752f));
}
__device__ __forceinline__ void ldsm_x4(uint32_t* r, uint32_t addr) {
    asm volatile("ldmatrix.sync.aligned.m8n8.x4.shared.b16 {%0,%1,%2,%3}, [%4];"
                 : "=r"(r[0]), "=r"(r[1]), "=r"(r[2]), "=r"(r[3]) : "r"(addr));
}
__device__ __forceinline__ void mma16816(float* d, const uint32_t* a, uint32_t b0, uint32_t b1) {
    asm volatile(
        "mma.sync.aligned.m16n8k16.row.col.f32.bf16.bf16.f32 "
        "{%0,%1,%2,%3}, {%4,%5,%6,%7}, {%8,%9}, {%0,%1,%2,%3};"
        : "+f"(d[0]), "+f"(d[1]), "+f"(d[2]), "+f"(d[3])
        : "r"(a[0]), "r"(a[1]), "r"(a[2]), "r"(a[3]), "r"(b0), "r"(b1));
}
__device__ __forceinline__ void cpasync16(uint32_t smem, const void* gptr) {
    asm volatile("cp.async.cg.shared.global [%0], [%1], 16;" :: "r"(smem), "l"(gptr));
}
__device__ __forceinline__ void cpasync_commit() {
    asm volatile("cp.async.commit_group;" ::: "memory");
}
template<int N> __device__ __forceinline__ void cpasync_wait() {
    asm volatile("cp.async.wait_group %0;" :: "n"(N) : "memory");
}

// ---------------- all weights f32 -> bf16 in one launch ----------------
#define NW_QKV (3*CC*CC)
#define NW_PRJ (CC*CC)
#define NW_FC1 (HIDDEN*CC)
#define NW_FC2 (CC*HIDDEN)
#define NW_ALL (NW_QKV+NW_PRJ+NW_FC1+NW_FC2)

__global__ void k_f2b_all(const float* __restrict__ qkv_w, const float* __restrict__ proj_w,
                          const float* __restrict__ fc1_w, const float* __restrict__ fc2_w) {
    int i = blockIdx.x * 256 + threadIdx.x;
    if (i < NW_QKV) { g_wqkv[i] = __float2bfloat16(qkv_w[i]); return; }
    i -= NW_QKV;
    if (i < NW_PRJ) { g_wproj[i] = __float2bfloat16(proj_w[i]); return; }
    i -= NW_PRJ;
    if (i < NW_FC1) { g_wfc1[i] = __float2bfloat16(fc1_w[i]); return; }
    i -= NW_FC1;
    if (i < NW_FC2) { g_wfc2[i] = __float2bfloat16(fc2_w[i]); }
}

// ---------------- precompute bias+mask table ----------------
__global__ void k_bias(const float* __restrict__ rpb, const int* __restrict__ relidx,
                       const float* __restrict__ amask) {
    int wh = blockIdx.x;
    int win = wh / NHEADS, h = wh % NHEADS;
    for (int i = threadIdx.x; i < TOK*TOK; i += 256)
        g_bm[(size_t)wh * (TOK*TOK) + i] = rpb[relidx[i] * NHEADS + h] + amask[win * (TOK*TOK) + i];
}

// ---------------- LN1 + roll(-3,-3) + window partition -> bf16 (8 tokens/block) ----------------
__global__ void __launch_bounds__(CC) k_ln1_shift_part(const float* __restrict__ x,
                                 const float* __restrict__ g,
                                 const float* __restrict__ b) {
    int c = threadIdx.x;
    float gc = g[c], bc = b[c];
    __shared__ float sh1[6], sh2[6];
    int lane = c & 31, warp = c >> 5;

    #pragma unroll 1
    for (int it = 0; it < 8; it++) {
        int w = blockIdx.x * 8 + it;
        int n = w / TOK, t = w % TOK;
        int img = n / NWIN_I, win = n % NWIN_I;
        int hs = (win / 8) * WSZ + t / WSZ;
        int ws = (win % 8) * WSZ + t % WSZ;
        int hsrc = (hs + SHIFT) % HH;
        int wsrc = (ws + SHIFT) % WW;
        float val = x[((size_t)img * (HH*WW) + hsrc * WW + wsrc) * CC + c];

        float s  = warp_sum(val);
        float s2 = warp_sum(val * val);
        if (lane == 0) { sh1[warp] = s; sh2[warp] = s2; }
        __syncthreads();
        float ts = 0.f, ts2 = 0.f;
        #pragma unroll
        for (int i = 0; i < 6; i++) { ts += sh1[i]; ts2 += sh2[i]; }
        float mean = ts * (1.0f / CC);
        float var  = ts2 * (1.0f / CC) - mean * mean;
        float inv  = rsqrtf(var + 1e-5f);
        g_xw[(size_t)w * CC + c] = __float2bfloat16((val - mean) * inv * gc + bc);
        __syncthreads();
    }
}

// ---------------- window reverse + roll(+3,+3) + residual + LN2 (8 tokens/block) ----------------
__global__ void __launch_bounds__(CC) k_resid_ln2(const float* __restrict__ x,
                            const float* __restrict__ g,
                            const float* __restrict__ b) {
    int c = threadIdx.x;
    float gc = g[c], bc = b[c];
    __shared__ float sh1[6], sh2[6];
    int lane = c & 31, warp = c >> 5;

    #pragma unroll 1
    for (int it = 0; it < 8; it++) {
        int tok = blockIdx.x * 8 + it;
        int img = tok / (HH*WW);
        int hw  = tok % (HH*WW);
        int hh = hw / WW, ww = hw % WW;
        int hs = (hh + HH - SHIFT) % HH;
        int ws = (ww + WW - SHIFT) % WW;
        int win = (hs / WSZ) * 8 + (ws / WSZ);
        int t   = (hs % WSZ) * WSZ + (ws % WSZ);
        size_t widx = ((size_t)(img * NWIN_I + win) * TOK + t) * CC + c;
        float val = x[(size_t)tok * CC + c] + __bfloat162float(g_proj[widx]);
        g_x1[(size_t)tok * CC + c] = val;

        float s  = warp_sum(val);
        float s2 = warp_sum(val * val);
        if (lane == 0) { sh1[warp] = s; sh2[warp] = s2; }
        __syncthreads();
        float ts = 0.f, ts2 = 0.f;
        #pragma unroll
        for (int i = 0; i < 6; i++) { ts += sh1[i]; ts2 += sh2[i]; }
        float mean = ts * (1.0f / CC);
        float var  = ts2 * (1.0f / CC) - mean * mean;
        float inv  = rsqrtf(var + 1e-5f);
        g_ln2[(size_t)tok * CC + c] = __float2bfloat16((val - mean) * inv * gc + bc);
        __syncthreads();
    }
}

// ---------------- HMMA GEMM, cp.async double buffer, ONE sync/iter ----------------
#define ASTR 40
#define BSTR 40
#define A_ST (128*ASTR)
#define B_ST (64*BSTR)

__global__ void __launch_bounds__(256, 3) k_gemm_mma(
        const __nv_bfloat16* __restrict__ A, const __nv_bfloat16* __restrict__ W,
        const float* __restrict__ bias, const float* __restrict__ res,
        void* __restrict__ outp, int M, int N, int K, int epi) {
    __shared__ __nv_bfloat16 sA[2*A_ST];
    __shared__ __nv_bfloat16 sB[2*B_ST];

    int tid = threadIdx.x, lane = tid & 31, wid = tid >> 5;
    int warp_m = wid & 3, warp_n = wid >> 2;
    int gm0 = blockIdx.y * 128;
    int gn0 = blockIdx.x * 64;

    float acc[2][4][4];
    #pragma unroll
    for (int mi = 0; mi < 2; mi++)
        #pragma unroll
        for (int ni = 0; ni < 4; ni++)
            #pragma unroll
            for (int q = 0; q < 4; q++) acc[mi][ni][q] = 0.f;

    uint32_t sAu = smem_u32(sA), sBu = smem_u32(sB);
    int lrA = tid >> 2, lcA = (tid & 3) * 8;

    const __nv_bfloat16* Ag = A + (size_t)(gm0 + lrA) * K + lcA;
    const __nv_bfloat16* Wg = W + (size_t)(gn0 + lrA) * K + lcA;
    uint32_t sa_w = sAu + (lrA * ASTR + lcA) * 2;
    uint32_t sb_w = sBu + (lrA * BSTR + lcA) * 2;

    int nk = K >> 5;
    cpasync16(sa_w,              Ag);
    cpasync16(sa_w + 64*ASTR*2,  Ag + (size_t)64 * K);
    cpasync16(sb_w,              Wg);
    cpasync_commit();

    for (int ch = 0; ch < nk; ch++) {
        int st = ch & 1;
        cpasync_wait<0>();
        __syncthreads();
        if (ch + 1 < nk) {
            int st2 = st ^ 1;
            const __nv_bfloat16* Ag2 = Ag + (ch + 1) * 32;
            const __nv_bfloat16* Wg2 = Wg + (ch + 1) * 32;
            cpasync16(sa_w + st2 * A_ST * 2,             Ag2);
            cpasync16(sa_w + (st2 * A_ST + 64*ASTR) * 2, Ag2 + (size_t)64 * K);
            cpasync16(sb_w + st2 * B_ST * 2,             Wg2);
            cpasync_commit();
        }

        uint32_t aAddr = sAu + (st * A_ST + (warp_m * 32 + (lane & 15)) * ASTR + (lane >> 4) * 8) * 2;
        uint32_t bAddr = sBu + (st * B_ST + (warp_n * 32 + (lane & 15)) * BSTR + (lane >> 4) * 8) * 2;
        #pragma unroll
        for (int ks = 0; ks < 2; ks++) {
            uint32_t a[2][4], b[2][4];
            #pragma unroll
            for (int mi = 0; mi < 2; mi++)
                ldsm_x4(a[mi], aAddr + (mi * 16 * ASTR + ks * 16) * 2);
            #pragma unroll
            for (int nj = 0; nj < 2; nj++)
                ldsm_x4(b[nj], bAddr + (nj * 16 * BSTR + ks * 16) * 2);
            #pragma unroll
            for (int mi = 0; mi < 2; mi++)
                #pragma unroll
                for (int ni = 0; ni < 4; ni++)
                    mma16816(acc[mi][ni], a[mi], b[ni >> 1][ni & 1], b[ni >> 1][2 + (ni & 1)]);
        }
    }

    // epilogue
    int row_base = gm0 + warp_m * 32 + (lane >> 2);
    int col_base = gn0 + warp_n * 32 + (lane & 3) * 2;

    #pragma unroll
    for (int mi = 0; mi < 2; mi++) {
        #pragma unroll
        for (int ni = 0; ni < 4; ni++) {
            int col = col_base + ni * 8;
            float bc0 = bias[col], bc1 = bias[col + 1];
            #pragma unroll
            for (int h = 0; h < 2; h++) {
                int r = row_base + mi * 16 + h * 8;
                float v0 = acc[mi][ni][h * 2 + 0] + bc0;
                float v1 = acc[mi][ni][h * 2 + 1] + bc1;
                if (epi == 1) { v0 = gelu_exact(v0); v1 = gelu_exact(v1); }
                if (epi == 2) {
                    float* out = (float*)outp;
                    const float2 rv = *reinterpret_cast<const float2*>(res + (size_t)r * N + col);
                    float2 o; o.x = v0 + rv.x; o.y = v1 + rv.y;
                    *reinterpret_cast<float2*>(out + (size_t)r * N + col) = o;
                } else {
                    __nv_bfloat16* out = (__nv_bfloat16*)outp;
                    __nv_bfloat162 p = __floats2bfloat162_rn(v0, v1);
                    *reinterpret_cast<uint32_t*>(out + (size_t)r * N + col) =
                        *reinterpret_cast<uint32_t*>(&p);
                }
            }
        }
    }
}

// ---------------- tensor-core windowed attention ----------------
// one block per (window, head); 4 warps; tokens padded 49 -> 64.
// S = Q K^T via mma (warp w owns rows w*16..w*16+15), softmax on fragments,
// P fragments reused directly as A operand of P * V^T.
#define QSTR 40    // Q/K smem row stride (bf16)
#define VSTR 72    // V^T smem row stride (bf16)

__global__ void __launch_bounds__(128) k_attn_tc() {
    int blk = blockIdx.x;
    int n = blk / NHEADS, head = blk % NHEADS;
    int win = n % NWIN_I;

    __shared__ __nv_bfloat16 sQ[64 * QSTR];
    __shared__ __nv_bfloat16 sK[64 * QSTR];
    __shared__ __nv_bfloat16 sVt[32 * VSTR];

    int tid = threadIdx.x, lane = tid & 31, warp = tid >> 5;
    const float scale = 0.17677669529663687f;   // 1/sqrt(32)

    // zero-fill (padding rows/cols must be 0)
    {
        uint32_t* z1 = reinterpret_cast<uint32_t*>(sQ);
        uint32_t* z2 = reinterpret_cast<uint32_t*>(sK);
        for (int i = tid; i < 64*QSTR/2; i += 128) { z1[i] = 0u; z2[i] = 0u; }
        uint32_t* z3 = reinterpret_cast<uint32_t*>(sVt);
        for (int i = tid; i < 32*VSTR/2; i += 128) z3[i] = 0u;
    }
    __syncthreads();

    // load Q (scaled), K as rows [t][d]; V transposed [d][t]
    const __nv_bfloat16* base = g_qkv + (size_t)n * TOK * (3*CC) + head * HD;
    for (int i = tid; i < TOK * 16; i += 128) {
        int t = i >> 4, d2 = (i & 15) * 2;
        const __nv_bfloat16* p = base + t * (3*CC) + d2;
        float2 q2 = __bfloat1622float2(*reinterpret_cast<const __nv_bfloat162*>(p));
        __nv_bfloat162 qs = __floats2bfloat162_rn(q2.x * scale, q2.y * scale);
        *reinterpret_cast<uint32_t*>(sQ + t * QSTR + d2) = *reinterpret_cast<uint32_t*>(&qs);
        *reinterpret_cast<uint32_t*>(sK + t * QSTR + d2) =
            *reinterpret_cast<const uint32_t*>(p + CC);
        __nv_bfloat162 v2 = *reinterpret_cast<const __nv_bfloat162*>(p + 2*CC);
        sVt[d2 * VSTR + t]       = v2.x;
        sVt[(d2 + 1) * VSTR + t] = v2.y;
    }
    __syncthreads();

    uint32_t sQu = smem_u32(sQ), sKu = smem_u32(sK), sVu = smem_u32(sVt);

    // ---- S = Q K^T : warp rows [warp*16, +16), cols 0..63 (8 n-tiles) ----
    float sacc[8][4];
    #pragma unroll
    for (int j = 0; j < 8; j++)
        #pragma unroll
        for (int q = 0; q < 4; q++) sacc[j][q] = 0.f;

    uint32_t qAddr = sQu + ((warp * 16 + (lane & 15)) * QSTR + (lane >> 4) * 8) * 2;
    #pragma unroll
    for (int kc = 0; kc < 2; kc++) {
        uint32_t aq[4];
        ldsm_x4(aq, qAddr + kc * 32);          // +16 bf16 = 32 B
        #pragma unroll
        for (int jj = 0; jj < 4; jj++) {
            uint32_t bk[4];
            ldsm_x4(bk, sKu + ((jj * 16 + (lane & 15)) * QSTR + (lane >> 4) * 8 + kc * 16) * 2);
            mma16816(sacc[jj*2 + 0], aq, bk[0], bk[2]);
            mma16816(sacc[jj*2 + 1], aq, bk[1], bk[3]);
        }
    }

    // ---- bias + mask + softmax on fragments ----
    int g = lane >> 2, qq = lane & 3;
    int r0 = warp * 16 + g, r1 = r0 + 8;
    const float* bmrow = g_bm + (size_t)(win * NHEADS + head) * (TOK*TOK);

    float m0 = -1e30f, m1 = -1e30f;
    #pragma unroll
    for (int j = 0; j < 8; j++) {
        int t0 = j * 8 + qq * 2, t1 = t0 + 1;
        float b00 = (t0 < TOK) ? ((r0 < TOK) ? bmrow[r0*TOK + t0] : 0.f) : -1e30f;
        float b01 = (t1 < TOK) ? ((r0 < TOK) ? bmrow[r0*TOK + t1] : 0.f) : -1e30f;
        float b10 = (t0 < TOK) ? ((r1 < TOK) ? bmrow[r1*TOK + t0] : 0.f) : -1e30f;
        float b11 = (t1 < TOK) ? ((r1 < TOK) ? bmrow[r1*TOK + t1] : 0.f) : -1e30f;
        sacc[j][0] += b00; sacc[j][1] += b01;
        sacc[j][2] += b10; sacc[j][3] += b11;
        m0 = fmaxf(m0, fmaxf(sacc[j][0], sacc[j][1]));
        m1 = fmaxf(m1, fmaxf(sacc[j][2], sacc[j][3]));
    }
    m0 = fmaxf(m0, __shfl_xor_sync(0xffffffffu, m0, 1));
    m0 = fmaxf(m0, __shfl_xor_sync(0xffffffffu, m0, 2));
    m1 = fmaxf(m1, __shfl_xor_sync(0xffffffffu, m1, 1));
    m1 = fmaxf(m1, __shfl_xor_sync(0xffffffffu, m1, 2));

    float sum0 = 0.f, sum1 = 0.f;
    #pragma unroll
    for (int j = 0; j < 8; j++) {
        sacc[j][0] = __expf(sacc[j][0] - m0);
        sacc[j][1] = __expf(sacc[j][1] - m0);
        sacc[j][2] = __expf(sacc[j][2] - m1);
        sacc[j][3] = __expf(sacc[j][3] - m1);
        sum0 += sacc[j][0] + sacc[j][1];
        sum1 += sacc[j][2] + sacc[j][3];
    }
    sum0 += __shfl_xor_sync(0xffffffffu, sum0, 1);
    sum0 += __shfl_xor_sync(0xffffffffu, sum0, 2);
    sum1 += __shfl_xor_sync(0xffffffffu, sum1, 1);
    sum1 += __shfl_xor_sync(0xffffffffu, sum1, 2);
    float inv0 = 1.0f / sum0, inv1 = 1.0f / sum1;

    // normalized P -> bf16 fragments (C layout == A layout identity)
    uint32_t pr0[8], pr1[8];
    #pragma unroll
    for (int j = 0; j < 8; j++) {
        __nv_bfloat162 p0 = __floats2bfloat162_rn(sacc[j][0] * inv0, sacc[j][1] * inv0);
        __nv_bfloat162 p1 = __floats2bfloat162_rn(sacc[j][2] * inv1, sacc[j][3] * inv1);
        pr0[j] = *reinterpret_cast<uint32_t*>(&p0);
        pr1[j] = *reinterpret_cast<uint32_t*>(&p1);
    }

    // ---- O = P * V^T : rows 16 x cols 32 (4 n-tiles), k = 64 tokens (4 chunks) ----
    float oacc[4][4];
    #pragma unroll
    for (int nt = 0; nt < 4; nt++)
        #pragma unroll
        for (int q = 0; q < 4; q++) oacc[nt][q] = 0.f;

    #pragma unroll
    for (int kk = 0; kk < 4; kk++) {
        uint32_t aP[4] = { pr0[2*kk], pr1[2*kk], pr0[2*kk+1], pr1[2*kk+1] };
        #pragma unroll
        for (int nn = 0; nn < 2; nn++) {
            uint32_t bv[4];
            ldsm_x4(bv, sVu + ((nn * 16 + (lane & 15)) * VSTR + (lane >> 4) * 8 + kk * 16) * 2);
            mma16816(oacc[nn*2 + 0], aP, bv[0], bv[2]);
            mma16816(oacc[nn*2 + 1], aP, bv[1], bv[3]);
        }
    }

    // ---- write O (rows < 49) ----
    __nv_bfloat16* outb = g_att + (size_t)n * TOK * CC + head * HD;
    #pragma unroll
    for (int nt = 0; nt < 4; nt++) {
        int col = nt * 8 + qq * 2;
        if (r0 < TOK) {
            __nv_bfloat162 o = __floats2bfloat162_rn(oacc[nt][0], oacc[nt][1]);
            *reinterpret_cast<uint32_t*>(outb + (size_t)r0 * CC + col) =
                *reinterpret_cast<uint32_t*>(&o);
        }
        if (r1 < TOK) {
            __nv_bfloat162 o = __floats2bfloat162_rn(oacc[nt][2], oacc[nt][3]);
            *reinterpret_cast<uint32_t*>(outb + (size_t)r1 * CC + col) =
                *reinterpret_cast<uint32_t*>(&o);
        }
    }
}

// ---------------- launch ----------------
extern "C" void kernel_launch(void* const* d_in, const int* in_sizes, int n_in,
                              void* d_out, int out_size) {
    const float* x       = (const float*)d_in[0];
    const float* norm1_g = (const float*)d_in[1];
    const float* norm1_b = (const float*)d_in[2];
    const float* qkv_w   = (const float*)d_in[3];
    const float* qkv_b   = (const float*)d_in[4];
    const float* rpb     = (const float*)d_in[5];
    const float* proj_w  = (const float*)d_in[6];
    const float* proj_b  = (const float*)d_in[7];
    const float* norm2_g = (const float*)d_in[8];
    const float* norm2_b = (const float*)d_in[9];
    const float* fc1_w   = (const float*)d_in[10];
    const float* fc1_b   = (const float*)d_in[11];
    const float* fc2_w   = (const float*)d_in[12];
    const float* fc2_b   = (const float*)d_in[13];
    const int*   relidx;
    const float* amask;
    if (in_sizes[14] == TOK * TOK) {
        relidx = (const int*)d_in[14];  amask = (const float*)d_in[15];
    } else {
        relidx = (const int*)d_in[15];  amask = (const float*)d_in[14];
    }
    float* out = (float*)d_out;

    __nv_bfloat16 *p_xw, *p_qkv, *p_att, *p_proj, *p_ln2, *p_hid;
    __nv_bfloat16 *p_wqkv, *p_wproj, *p_wfc1, *p_wfc2;
    float *p_x1;
    cudaGetSymbolAddress((void**)&p_xw,    g_xw);
    cudaGetSymbolAddress((void**)&p_qkv,   g_qkv);
    cudaGetSymbolAddress((void**)&p_att,   g_att);
    cudaGetSymbolAddress((void**)&p_proj,  g_proj);
    cudaGetSymbolAddress((void**)&p_x1,    g_x1);
    cudaGetSymbolAddress((void**)&p_ln2,   g_ln2);
    cudaGetSymbolAddress((void**)&p_hid,   g_hid);
    cudaGetSymbolAddress((void**)&p_wqkv,  g_wqkv);
    cudaGetSymbolAddress((void**)&p_wproj, g_wproj);
    cudaGetSymbolAddress((void**)&p_wfc1,  g_wfc1);
    cudaGetSymbolAddress((void**)&p_wfc2,  g_wfc2);

    k_f2b_all<<<NW_ALL/256, 256>>>(qkv_w, proj_w, fc1_w, fc2_w);
    k_bias<<<NWIN_I*NHEADS, 256>>>(rpb, relidx, amask);

    k_ln1_shift_part<<<NTOK/8, CC>>>(x, norm1_g, norm1_b);

    {
        dim3 grid((3*CC)/64, NTOK/128);
        k_gemm_mma<<<grid, 256>>>(p_xw, p_wqkv, qkv_b, nullptr, p_qkv, NTOK, 3*CC, CC, 0);
    }

    k_attn_tc<<<NWIN * NHEADS, 128>>>();

    {
        dim3 grid(CC/64, NTOK/128);
        k_gemm_mma<<<grid, 256>>>(p_att, p_wproj, proj_b, nullptr, p_proj, NTOK, CC, CC, 0);
    }

    k_resid_ln2<<<NTOK/8, CC>>>(x, norm2_g, norm2_b);

    {
        dim3 grid(HIDDEN/64, NTOK/128);
        k_gemm_mma<<<grid, 256>>>(p_ln2, p_wfc1, fc1_b, nullptr, p_hid, NTOK, HIDDEN, CC, 1);
    }

    {
        dim3 grid(CC/64, NTOK/128);
        k_gemm_mma<<<grid, 256>>>(p_hid, p_wfc2, fc2_b, p_x1, out, NTOK, CC, HIDDEN, 2);
    }
}

// round 8
// speedup vs baseline: 10.2449x; 1.2024x over previous
#include <cuda_runtime.h>
#include <cuda_bf16.h>
#include <math.h>
#include <stdint.h>

// ---------------- problem constants ----------------
#define BB     64
#define HH     56
#define WW     56
#define CC     192
#define NHEADS 6
#define HD     32
#define WSZ    7
#define TOK    49
#define NWIN_I 64
#define SHIFT  3
#define NTOK   (BB*HH*WW)   // 200704
#define NWIN   (BB*NWIN_I)  // 4096
#define HIDDEN 768

// ---------------- scratch (device globals; no allocs allowed) ----------------
__device__ __nv_bfloat16 g_xw  [(size_t)NTOK*CC];
__device__ __nv_bfloat16 g_qkv [(size_t)NTOK*3*CC];
__device__ __nv_bfloat16 g_att [(size_t)NTOK*CC];
__device__ __nv_bfloat16 g_proj[(size_t)NTOK*CC];
__device__ float         g_x1  [(size_t)NTOK*CC];
__device__ __nv_bfloat16 g_ln2 [(size_t)NTOK*CC];
__device__ __nv_bfloat16 g_hid [(size_t)NTOK*HIDDEN];
__device__ __nv_bfloat16 g_wqkv [3*CC*CC];
__device__ __nv_bfloat16 g_wproj[CC*CC];
__device__ __nv_bfloat16 g_wfc1 [HIDDEN*CC];
__device__ __nv_bfloat16 g_wfc2 [CC*HIDDEN];
__device__ float         g_bm  [NWIN_I*NHEADS*TOK*TOK];   // bias+mask table (3.7MB)

// ---------------- helpers ----------------
__device__ __forceinline__ uint32_t smem_u32(const void* p) {
    uint32_t a;
    asm("{ .reg .u64 t; cvta.to.shared.u64 t, %1; cvt.u32.u64 %0, t; }" : "=r"(a) : "l"(p));
    return a;
}
__device__ __forceinline__ float gelu_exact(float x) {
    return 0.5f * x * (1.0f + erff(x * 0.70710678118654752f));
}
__device__ __forceinline__ void ldsm_x4(uint32_t* r, uint32_t addr) {
    asm volatile("ldmatrix.sync.aligned.m8n8.x4.shared.b16 {%0,%1,%2,%3}, [%4];"
                 : "=r"(r[0]), "=r"(r[1]), "=r"(r[2]), "=r"(r[3]) : "r"(addr));
}
__device__ __forceinline__ void mma16816(float* d, const uint32_t* a, uint32_t b0, uint32_t b1) {
    asm volatile(
        "mma.sync.aligned.m16n8k16.row.col.f32.bf16.bf16.f32 "
        "{%0,%1,%2,%3}, {%4,%5,%6,%7}, {%8,%9}, {%0,%1,%2,%3};"
        : "+f"(d[0]), "+f"(d[1]), "+f"(d[2]), "+f"(d[3])
        : "r"(a[0]), "r"(a[1]), "r"(a[2]), "r"(a[3]), "r"(b0), "r"(b1));
}
__device__ __forceinline__ void cpasync16(uint32_t smem, const void* gptr) {
    asm volatile("cp.async.cg.shared.global [%0], [%1], 16;" :: "r"(smem), "l"(gptr));
}
__device__ __forceinline__ void cpasync_commit() {
    asm volatile("cp.async.commit_group;" ::: "memory");
}
template<int N> __device__ __forceinline__ void cpasync_wait() {
    asm volatile("cp.async.wait_group %0;" :: "n"(N) : "memory");
}

// ---------------- all weights f32 -> bf16 in one launch ----------------
#define NW_QKV (3*CC*CC)
#define NW_PRJ (CC*CC)
#define NW_FC1 (HIDDEN*CC)
#define NW_FC2 (CC*HIDDEN)
#define NW_ALL (NW_QKV+NW_PRJ+NW_FC1+NW_FC2)

__global__ void k_f2b_all(const float* __restrict__ qkv_w, const float* __restrict__ proj_w,
                          const float* __restrict__ fc1_w, const float* __restrict__ fc2_w) {
    int i = blockIdx.x * 256 + threadIdx.x;
    if (i < NW_QKV) { g_wqkv[i] = __float2bfloat16(qkv_w[i]); return; }
    i -= NW_QKV;
    if (i < NW_PRJ) { g_wproj[i] = __float2bfloat16(proj_w[i]); return; }
    i -= NW_PRJ;
    if (i < NW_FC1) { g_wfc1[i] = __float2bfloat16(fc1_w[i]); return; }
    i -= NW_FC1;
    if (i < NW_FC2) { g_wfc2[i] = __float2bfloat16(fc2_w[i]); }
}

// ---------------- precompute bias+mask table ----------------
__global__ void k_bias(const float* __restrict__ rpb, const int* __restrict__ relidx,
                       const float* __restrict__ amask) {
    int wh = blockIdx.x;
    int win = wh / NHEADS, h = wh % NHEADS;
    for (int i = threadIdx.x; i < TOK*TOK; i += 256)
        g_bm[(size_t)wh * (TOK*TOK) + i] = rpb[relidx[i] * NHEADS + h] + amask[win * (TOK*TOK) + i];
}

// ---------------- LN1 + roll + window partition: warp-per-token, no barriers ----------------
__global__ void __launch_bounds__(256) k_ln1_shift_part(const float* __restrict__ x,
                                 const float* __restrict__ g,
                                 const float* __restrict__ b) {
    int lane = threadIdx.x & 31, warp = threadIdx.x >> 5;
    int w = blockIdx.x * 8 + warp;          // token index (window layout)
    int n = w / TOK, t = w % TOK;
    int img = n / NWIN_I, win = n % NWIN_I;
    int hs = (win / 8) * WSZ + t / WSZ;
    int ws = (win % 8) * WSZ + t % WSZ;
    int hsrc = (hs + SHIFT) % HH;
    int wsrc = (ws + SHIFT) % WW;
    const float* row = x + ((size_t)img * (HH*WW) + hsrc * WW + wsrc) * CC;

    float v[6];
    float s = 0.f, s2 = 0.f;
    #pragma unroll
    for (int j = 0; j < 6; j++) {
        v[j] = row[lane + 32*j];
        s += v[j]; s2 += v[j]*v[j];
    }
    #pragma unroll
    for (int o = 16; o > 0; o >>= 1) {
        s  += __shfl_xor_sync(0xffffffffu, s,  o);
        s2 += __shfl_xor_sync(0xffffffffu, s2, o);
    }
    float mean = s * (1.0f / CC);
    float var  = s2 * (1.0f / CC) - mean * mean;
    float inv  = rsqrtf(var + 1e-5f);
    __nv_bfloat16* outp = g_xw + (size_t)w * CC;
    #pragma unroll
    for (int j = 0; j < 6; j++) {
        int c = lane + 32*j;
        outp[c] = __float2bfloat16((v[j] - mean) * inv * g[c] + b[c]);
    }
}

// ---------------- window reverse + roll + residual + LN2: warp-per-token ----------------
__global__ void __launch_bounds__(256) k_resid_ln2(const float* __restrict__ x,
                            const float* __restrict__ g,
                            const float* __restrict__ b) {
    int lane = threadIdx.x & 31, warp = threadIdx.x >> 5;
    int tok = blockIdx.x * 8 + warp;
    int img = tok / (HH*WW);
    int hw  = tok % (HH*WW);
    int hh = hw / WW, ww = hw % WW;
    int hs = (hh + HH - SHIFT) % HH;
    int ws = (ww + WW - SHIFT) % WW;
    int win = (hs / WSZ) * 8 + (ws / WSZ);
    int t   = (hs % WSZ) * WSZ + (ws % WSZ);
    const __nv_bfloat16* prow = g_proj + ((size_t)(img * NWIN_I + win) * TOK + t) * CC;
    const float* xrow = x + (size_t)tok * CC;
    float* x1row = g_x1 + (size_t)tok * CC;

    float v[6];
    float s = 0.f, s2 = 0.f;
    #pragma unroll
    for (int j = 0; j < 6; j++) {
        int c = lane + 32*j;
        v[j] = xrow[c] + __bfloat162float(prow[c]);
        x1row[c] = v[j];
        s += v[j]; s2 += v[j]*v[j];
    }
    #pragma unroll
    for (int o = 16; o > 0; o >>= 1) {
        s  += __shfl_xor_sync(0xffffffffu, s,  o);
        s2 += __shfl_xor_sync(0xffffffffu, s2, o);
    }
    float mean = s * (1.0f / CC);
    float var  = s2 * (1.0f / CC) - mean * mean;
    float inv  = rsqrtf(var + 1e-5f);
    __nv_bfloat16* outp = g_ln2 + (size_t)tok * CC;
    #pragma unroll
    for (int j = 0; j < 6; j++) {
        int c = lane + 32*j;
        outp[c] = __float2bfloat16((v[j] - mean) * inv * g[c] + b[c]);
    }
}

// ---------------- HMMA GEMM, 3-stage cp.async pipeline ----------------
// C[M,N] = A[M,K] @ W[N,K]^T + bias. BM=128, BN=64, BK=32; 256 thr, warp grid 4x2.
// epi: 0 = bf16 out, 1 = bf16 + gelu, 2 = f32 + residual
#define ASTR 40
#define BSTR 40
#define A_ST (128*ASTR)
#define B_ST (64*BSTR)

__global__ void __launch_bounds__(256, 3) k_gemm_mma(
        const __nv_bfloat16* __restrict__ A, const __nv_bfloat16* __restrict__ W,
        const float* __restrict__ bias, const float* __restrict__ res,
        void* __restrict__ outp, int M, int N, int K, int epi) {
    __shared__ __nv_bfloat16 sA[3*A_ST];
    __shared__ __nv_bfloat16 sB[3*B_ST];

    int tid = threadIdx.x, lane = tid & 31, wid = tid >> 5;
    int warp_m = wid & 3, warp_n = wid >> 2;
    int gm0 = blockIdx.y * 128;
    int gn0 = blockIdx.x * 64;

    float acc[2][4][4];
    #pragma unroll
    for (int mi = 0; mi < 2; mi++)
        #pragma unroll
        for (int ni = 0; ni < 4; ni++)
            #pragma unroll
            for (int q = 0; q < 4; q++) acc[mi][ni][q] = 0.f;

    uint32_t sAu = smem_u32(sA), sBu = smem_u32(sB);
    int lrA = tid >> 2, lcA = (tid & 3) * 8;

    const __nv_bfloat16* Ag = A + (size_t)(gm0 + lrA) * K + lcA;
    const __nv_bfloat16* Wg = W + (size_t)(gn0 + lrA) * K + lcA;
    uint32_t sa_w = sAu + (lrA * ASTR + lcA) * 2;
    uint32_t sb_w = sBu + (lrA * BSTR + lcA) * 2;

    int nk = K >> 5;
    // prologue: stages 0,1
    #pragma unroll
    for (int s = 0; s < 2; s++) {
        cpasync16(sa_w + s * A_ST * 2,             Ag + s * 32);
        cpasync16(sa_w + (s * A_ST + 64*ASTR) * 2, Ag + s * 32 + (size_t)64 * K);
        cpasync16(sb_w + s * B_ST * 2,             Wg + s * 32);
        cpasync_commit();
    }

    int st = 0;
    for (int ch = 0; ch < nk; ch++) {
        if (ch + 1 < nk) cpasync_wait<1>(); else cpasync_wait<0>();
        __syncthreads();
        if (ch + 2 < nk) {
            int st2 = st + 2; if (st2 >= 3) st2 -= 3;
            const __nv_bfloat16* Ag2 = Ag + (ch + 2) * 32;
            const __nv_bfloat16* Wg2 = Wg + (ch + 2) * 32;
            cpasync16(sa_w + st2 * A_ST * 2,             Ag2);
            cpasync16(sa_w + (st2 * A_ST + 64*ASTR) * 2, Ag2 + (size_t)64 * K);
            cpasync16(sb_w + st2 * B_ST * 2,             Wg2);
            cpasync_commit();
        }

        uint32_t aAddr = sAu + (st * A_ST + (warp_m * 32 + (lane & 15)) * ASTR + (lane >> 4) * 8) * 2;
        uint32_t bAddr = sBu + (st * B_ST + (warp_n * 32 + (lane & 15)) * BSTR + (lane >> 4) * 8) * 2;
        #pragma unroll
        for (int ks = 0; ks < 2; ks++) {
            uint32_t a[2][4], b[2][4];
            #pragma unroll
            for (int mi = 0; mi < 2; mi++)
                ldsm_x4(a[mi], aAddr + (mi * 16 * ASTR + ks * 16) * 2);
            #pragma unroll
            for (int nj = 0; nj < 2; nj++)
                ldsm_x4(b[nj], bAddr + (nj * 16 * BSTR + ks * 16) * 2);
            #pragma unroll
            for (int mi = 0; mi < 2; mi++)
                #pragma unroll
                for (int ni = 0; ni < 4; ni++)
                    mma16816(acc[mi][ni], a[mi], b[ni >> 1][ni & 1], b[ni >> 1][2 + (ni & 1)]);
        }
        if (++st == 3) st = 0;
    }

    // epilogue
    int row_base = gm0 + warp_m * 32 + (lane >> 2);
    int col_base = gn0 + warp_n * 32 + (lane & 3) * 2;

    #pragma unroll
    for (int mi = 0; mi < 2; mi++) {
        #pragma unroll
        for (int ni = 0; ni < 4; ni++) {
            int col = col_base + ni * 8;
            float bc0 = bias[col], bc1 = bias[col + 1];
            #pragma unroll
            for (int h = 0; h < 2; h++) {
                int r = row_base + mi * 16 + h * 8;
                float v0 = acc[mi][ni][h * 2 + 0] + bc0;
                float v1 = acc[mi][ni][h * 2 + 1] + bc1;
                if (epi == 1) { v0 = gelu_exact(v0); v1 = gelu_exact(v1); }
                if (epi == 2) {
                    float* out = (float*)outp;
                    const float2 rv = *reinterpret_cast<const float2*>(res + (size_t)r * N + col);
                    float2 o; o.x = v0 + rv.x; o.y = v1 + rv.y;
                    *reinterpret_cast<float2*>(out + (size_t)r * N + col) = o;
                } else {
                    __nv_bfloat16* out = (__nv_bfloat16*)outp;
                    __nv_bfloat162 p = __floats2bfloat162_rn(v0, v1);
                    *reinterpret_cast<uint32_t*>(out + (size_t)r * N + col) =
                        *reinterpret_cast<uint32_t*>(&p);
                }
            }
        }
    }
}

// ---------------- tensor-core windowed attention ----------------
#define QSTR 40    // Q/K smem row stride (bf16)
#define VSTR 72    // V^T smem row stride (bf16)

__global__ void __launch_bounds__(128) k_attn_tc() {
    int blk = blockIdx.x;
    int n = blk / NHEADS, head = blk % NHEADS;
    int win = n % NWIN_I;

    __shared__ __nv_bfloat16 sQ[64 * QSTR];
    __shared__ __nv_bfloat16 sK[64 * QSTR];
    __shared__ __nv_bfloat16 sVt[32 * VSTR];

    int tid = threadIdx.x, lane = tid & 31, warp = tid >> 5;
    const float scale = 0.17677669529663687f;

    {
        uint32_t* z1 = reinterpret_cast<uint32_t*>(sQ);
        uint32_t* z2 = reinterpret_cast<uint32_t*>(sK);
        for (int i = tid; i < 64*QSTR/2; i += 128) { z1[i] = 0u; z2[i] = 0u; }
        uint32_t* z3 = reinterpret_cast<uint32_t*>(sVt);
        for (int i = tid; i < 32*VSTR/2; i += 128) z3[i] = 0u;
    }
    __syncthreads();

    const __nv_bfloat16* base = g_qkv + (size_t)n * TOK * (3*CC) + head * HD;
    for (int i = tid; i < TOK * 16; i += 128) {
        int t = i >> 4, d2 = (i & 15) * 2;
        const __nv_bfloat16* p = base + t * (3*CC) + d2;
        float2 q2 = __bfloat1622float2(*reinterpret_cast<const __nv_bfloat162*>(p));
        __nv_bfloat162 qs = __floats2bfloat162_rn(q2.x * scale, q2.y * scale);
        *reinterpret_cast<uint32_t*>(sQ + t * QSTR + d2) = *reinterpret_cast<uint32_t*>(&qs);
        *reinterpret_cast<uint32_t*>(sK + t * QSTR + d2) =
            *reinterpret_cast<const uint32_t*>(p + CC);
        __nv_bfloat162 v2 = *reinterpret_cast<const __nv_bfloat162*>(p + 2*CC);
        sVt[d2 * VSTR + t]       = v2.x;
        sVt[(d2 + 1) * VSTR + t] = v2.y;
    }
    __syncthreads();

    uint32_t sQu = smem_u32(sQ), sKu = smem_u32(sK), sVu = smem_u32(sVt);

    float sacc[8][4];
    #pragma unroll
    for (int j = 0; j < 8; j++)
        #pragma unroll
        for (int q = 0; q < 4; q++) sacc[j][q] = 0.f;

    uint32_t qAddr = sQu + ((warp * 16 + (lane & 15)) * QSTR + (lane >> 4) * 8) * 2;
    #pragma unroll
    for (int kc = 0; kc < 2; kc++) {
        uint32_t aq[4];
        ldsm_x4(aq, qAddr + kc * 32);
        #pragma unroll
        for (int jj = 0; jj < 4; jj++) {
            uint32_t bk[4];
            ldsm_x4(bk, sKu + ((jj * 16 + (lane & 15)) * QSTR + (lane >> 4) * 8 + kc * 16) * 2);
            mma16816(sacc[jj*2 + 0], aq, bk[0], bk[2]);
            mma16816(sacc[jj*2 + 1], aq, bk[1], bk[3]);
        }
    }

    int g = lane >> 2, qq = lane & 3;
    int r0 = warp * 16 + g, r1 = r0 + 8;
    const float* bmrow = g_bm + (size_t)(win * NHEADS + head) * (TOK*TOK);

    float m0 = -1e30f, m1 = -1e30f;
    #pragma unroll
    for (int j = 0; j < 8; j++) {
        int t0 = j * 8 + qq * 2, t1 = t0 + 1;
        float b00 = (t0 < TOK) ? ((r0 < TOK) ? bmrow[r0*TOK + t0] : 0.f) : -1e30f;
        float b01 = (t1 < TOK) ? ((r0 < TOK) ? bmrow[r0*TOK + t1] : 0.f) : -1e30f;
        float b10 = (t0 < TOK) ? ((r1 < TOK) ? bmrow[r1*TOK + t0] : 0.f) : -1e30f;
        float b11 = (t1 < TOK) ? ((r1 < TOK) ? bmrow[r1*TOK + t1] : 0.f) : -1e30f;
        sacc[j][0] += b00; sacc[j][1] += b01;
        sacc[j][2] += b10; sacc[j][3] += b11;
        m0 = fmaxf(m0, fmaxf(sacc[j][0], sacc[j][1]));
        m1 = fmaxf(m1, fmaxf(sacc[j][2], sacc[j][3]));
    }
    m0 = fmaxf(m0, __shfl_xor_sync(0xffffffffu, m0, 1));
    m0 = fmaxf(m0, __shfl_xor_sync(0xffffffffu, m0, 2));
    m1 = fmaxf(m1, __shfl_xor_sync(0xffffffffu, m1, 1));
    m1 = fmaxf(m1, __shfl_xor_sync(0xffffffffu, m1, 2));

    float sum0 = 0.f, sum1 = 0.f;
    #pragma unroll
    for (int j = 0; j < 8; j++) {
        sacc[j][0] = __expf(sacc[j][0] - m0);
        sacc[j][1] = __expf(sacc[j][1] - m0);
        sacc[j][2] = __expf(sacc[j][2] - m1);
        sacc[j][3] = __expf(sacc[j][3] - m1);
        sum0 += sacc[j][0] + sacc[j][1];
        sum1 += sacc[j][2] + sacc[j][3];
    }
    sum0 += __shfl_xor_sync(0xffffffffu, sum0, 1);
    sum0 += __shfl_xor_sync(0xffffffffu, sum0, 2);
    sum1 += __shfl_xor_sync(0xffffffffu, sum1, 1);
    sum1 += __shfl_xor_sync(0xffffffffu, sum1, 2);
    float inv0 = 1.0f / sum0, inv1 = 1.0f / sum1;

    uint32_t pr0[8], pr1[8];
    #pragma unroll
    for (int j = 0; j < 8; j++) {
        __nv_bfloat162 p0 = __floats2bfloat162_rn(sacc[j][0] * inv0, sacc[j][1] * inv0);
        __nv_bfloat162 p1 = __floats2bfloat162_rn(sacc[j][2] * inv1, sacc[j][3] * inv1);
        pr0[j] = *reinterpret_cast<uint32_t*>(&p0);
        pr1[j] = *reinterpret_cast<uint32_t*>(&p1);
    }

    float oacc[4][4];
    #pragma unroll
    for (int nt = 0; nt < 4; nt++)
        #pragma unroll
        for (int q = 0; q < 4; q++) oacc[nt][q] = 0.f;

    #pragma unroll
    for (int kk = 0; kk < 4; kk++) {
        uint32_t aP[4] = { pr0[2*kk], pr1[2*kk], pr0[2*kk+1], pr1[2*kk+1] };
        #pragma unroll
        for (int nn = 0; nn < 2; nn++) {
            uint32_t bv[4];
            ldsm_x4(bv, sVu + ((nn * 16 + (lane & 15)) * VSTR + (lane >> 4) * 8 + kk * 16) * 2);
            mma16816(oacc[nn*2 + 0], aP, bv[0], bv[2]);
            mma16816(oacc[nn*2 + 1], aP, bv[1], bv[3]);
        }
    }

    __nv_bfloat16* outb = g_att + (size_t)n * TOK * CC + head * HD;
    #pragma unroll
    for (int nt = 0; nt < 4; nt++) {
        int col = nt * 8 + qq * 2;
        if (r0 < TOK) {
            __nv_bfloat162 o = __floats2bfloat162_rn(oacc[nt][0], oacc[nt][1]);
            *reinterpret_cast<uint32_t*>(outb + (size_t)r0 * CC + col) =
                *reinterpret_cast<uint32_t*>(&o);
        }
        if (r1 < TOK) {
            __nv_bfloat162 o = __floats2bfloat162_rn(oacc[nt][2], oacc[nt][3]);
            *reinterpret_cast<uint32_t*>(outb + (size_t)r1 * CC + col) =
                *reinterpret_cast<uint32_t*>(&o);
        }
    }
}

// ---------------- launch ----------------
extern "C" void kernel_launch(void* const* d_in, const int* in_sizes, int n_in,
                              void* d_out, int out_size) {
    const float* x       = (const float*)d_in[0];
    const float* norm1_g = (const float*)d_in[1];
    const float* norm1_b = (const float*)d_in[2];
    const float* qkv_w   = (const float*)d_in[3];
    const float* qkv_b   = (const float*)d_in[4];
    const float* rpb     = (const float*)d_in[5];
    const float* proj_w  = (const float*)d_in[6];
    const float* proj_b  = (const float*)d_in[7];
    const float* norm2_g = (const float*)d_in[8];
    const float* norm2_b = (const float*)d_in[9];
    const float* fc1_w   = (const float*)d_in[10];
    const float* fc1_b   = (const float*)d_in[11];
    const float* fc2_w   = (const float*)d_in[12];
    const float* fc2_b   = (const float*)d_in[13];
    const int*   relidx;
    const float* amask;
    if (in_sizes[14] == TOK * TOK) {
        relidx = (const int*)d_in[14];  amask = (const float*)d_in[15];
    } else {
        relidx = (const int*)d_in[15];  amask = (const float*)d_in[14];
    }
    float* out = (float*)d_out;

    __nv_bfloat16 *p_xw, *p_qkv, *p_att, *p_proj, *p_ln2, *p_hid;
    __nv_bfloat16 *p_wqkv, *p_wproj, *p_wfc1, *p_wfc2;
    float *p_x1;
    cudaGetSymbolAddress((void**)&p_xw,    g_xw);
    cudaGetSymbolAddress((void**)&p_qkv,   g_qkv);
    cudaGetSymbolAddress((void**)&p_att,   g_att);
    cudaGetSymbolAddress((void**)&p_proj,  g_proj);
    cudaGetSymbolAddress((void**)&p_x1,    g_x1);
    cudaGetSymbolAddress((void**)&p_ln2,   g_ln2);
    cudaGetSymbolAddress((void**)&p_hid,   g_hid);
    cudaGetSymbolAddress((void**)&p_wqkv,  g_wqkv);
    cudaGetSymbolAddress((void**)&p_wproj, g_wproj);
    cudaGetSymbolAddress((void**)&p_wfc1,  g_wfc1);
    cudaGetSymbolAddress((void**)&p_wfc2,  g_wfc2);

    k_f2b_all<<<NW_ALL/256, 256>>>(qkv_w, proj_w, fc1_w, fc2_w);
    k_bias<<<NWIN_I*NHEADS, 256>>>(rpb, relidx, amask);

    k_ln1_shift_part<<<NTOK/8, 256>>>(x, norm1_g, norm1_b);

    {
        dim3 grid((3*CC)/64, NTOK/128);
        k_gemm_mma<<<grid, 256>>>(p_xw, p_wqkv, qkv_b, nullptr, p_qkv, NTOK, 3*CC, CC, 0);
    }

    k_attn_tc<<<NWIN * NHEADS, 128>>>();

    {
        dim3 grid(CC/64, NTOK/128);
        k_gemm_mma<<<grid, 256>>>(p_att, p_wproj, proj_b, nullptr, p_proj, NTOK, CC, CC, 0);
    }

    k_resid_ln2<<<NTOK/8, 256>>>(x, norm2_g, norm2_b);

    {
        dim3 grid(HIDDEN/64, NTOK/128);
        k_gemm_mma<<<grid, 256>>>(p_ln2, p_wfc1, fc1_b, nullptr, p_hid, NTOK, HIDDEN, CC, 1);
    }

    {
        dim3 grid(CC/64, NTOK/128);
        k_gemm_mma<<<grid, 256>>>(p_hid, p_wfc2, fc2_b, p_x1, out, NTOK, CC, HIDDEN, 2);
    }
}